// round 1
// baseline (speedup 1.0000x reference)
#include <cuda_runtime.h>
#include <cstddef>

#define NTOK 25600
#define FD   256
#define FHID 1024
#define IMH  160
#define IMW  160
#define NL   4

// ---------------- scratch (device globals; no allocs allowed) ----------------
__device__ float g_d  [NTOK*FD];
__device__ float g_xk [NTOK*FD];
__device__ float g_xv [NTOK*FD];
__device__ float g_xr [NTOK*FD];
__device__ float g_k  [NTOK*FD];
__device__ float g_v  [NTOK*FD];
__device__ float g_r  [NTOK*FD];
__device__ float g_rr [NTOK*FD];
__device__ float g_hid[NTOK*FHID];
__device__ float g_dw [NTOK*FD];
__device__ float g_wtT[49*FD];

// ---------------- helpers ----------------
__device__ __forceinline__ float wsum(float v) {
#pragma unroll
    for (int o = 16; o; o >>= 1) v += __shfl_xor_sync(0xffffffffu, v, o);
    return v;
}

__device__ __forceinline__ void ld8(const float* __restrict__ p, float v[8]) {
    float4 a = *(const float4*)p;
    float4 b = *(const float4*)(p + 4);
    v[0]=a.x; v[1]=a.y; v[2]=a.z; v[3]=a.w; v[4]=b.x; v[5]=b.y; v[6]=b.z; v[7]=b.w;
}
__device__ __forceinline__ void st8(float* __restrict__ p, const float v[8]) {
    float4 a{v[0],v[1],v[2],v[3]}, b{v[4],v[5],v[6],v[7]};
    *(float4*)p = a; *(float4*)(p + 4) = b;
}

// LayerNorm over 256 features: one warp per token, 8 features per lane.
__device__ __forceinline__ void ln_compute(int n, int lane,
                                           const float* __restrict__ lw,
                                           const float* __restrict__ lb,
                                           float xs[8]) {
    const float* row = g_d + (size_t)n * FD + lane * 8;
    float v[8]; ld8(row, v);
    float s = v[0]+v[1]+v[2]+v[3]+v[4]+v[5]+v[6]+v[7];
    float mu = wsum(s) * (1.f / 256.f);
    float q = 0.f;
#pragma unroll
    for (int t = 0; t < 8; t++) { float dd = v[t] - mu; q += dd * dd; }
    float rs = rsqrtf(wsum(q) * (1.f / 256.f) + 1e-5f);
    float wv[8], bv[8];
    ld8(lw + lane*8, wv); ld8(lb + lane*8, bv);
#pragma unroll
    for (int t = 0; t < 8; t++) xs[t] = (v[t] - mu) * rs * wv[t] + bv[t];
}

// ---------------- stem: 1x1 conv (1->256) + depthwise 7x7 + WSiLU ----------------
__global__ void stem_kernel(const float* __restrict__ x,
                            const float* __restrict__ w1, const float* __restrict__ b1,
                            const float* __restrict__ w2, const float* __restrict__ b2) {
    int n = blockIdx.x;
    int h = n / IMW, w = n % IMW;
    int c = threadIdx.x;
    __shared__ float sx[49];
    __shared__ float sm[49];
    if (threadIdx.x < 49) {
        int u = threadIdx.x / 7, vv = threadIdx.x % 7;
        int hh = h + u - 3, ww = w + vv - 3;
        bool in = (hh >= 0 && hh < IMH && ww >= 0 && ww < IMW);
        sx[threadIdx.x] = in ? x[hh * IMW + ww] : 0.f;
        sm[threadIdx.x] = in ? 1.f : 0.f;
    }
    __syncthreads();
    float a = w1[c], bb = b1[c];
    float acc = b2[c];
#pragma unroll
    for (int t = 0; t < 49; t++)
        acc += (sx[t] * a + bb * sm[t]) * w2[c * 49 + t];
    float s = 1.f / (1.f + expf(-4.f * acc));
    g_d[(size_t)n * FD + c] = s * acc;
}

// ---------------- LN kernels ----------------
__global__ void ln_plain_kernel(const float* __restrict__ lw, const float* __restrict__ lb) {
    int n = blockIdx.x * 8 + (threadIdx.x >> 5);
    int lane = threadIdx.x & 31;
    float xs[8];
    ln_compute(n, lane, lw, lb, xs);
    st8(g_d + (size_t)n * FD + lane * 8, xs);
}

__global__ void ln_mix3_kernel(const float* __restrict__ lw, const float* __restrict__ lb,
                               const float* __restrict__ tmk, const float* __restrict__ tmv,
                               const float* __restrict__ tmr, const float* __restrict__ sp) {
    int n = blockIdx.x * 8 + (threadIdx.x >> 5);
    int lane = threadIdx.x & 31;
    float xs[8];
    ln_compute(n, lane, lw, lb, xs);
    size_t base = (size_t)n * FD + lane * 8;
    int j = lane * 8;
    float spv[8], mk[8], mv[8], mr[8];
    ld8(sp + base, spv); ld8(tmk + j, mk); ld8(tmv + j, mv); ld8(tmr + j, mr);
    float ok[8], ov[8], orr[8];
#pragma unroll
    for (int t = 0; t < 8; t++) {
        ok[t]  = xs[t] * mk[t] + spv[t] * (1.f - mk[t]);
        ov[t]  = xs[t] * mv[t] + spv[t] * (1.f - mv[t]);
        orr[t] = xs[t] * mr[t] + spv[t] * (1.f - mr[t]);
    }
    st8(g_xk + base, ok); st8(g_xv + base, ov); st8(g_xr + base, orr);
}

__global__ void ln_mix2_kernel(const float* __restrict__ lw, const float* __restrict__ lb,
                               const float* __restrict__ tmk, const float* __restrict__ tmr,
                               const float* __restrict__ sp) {
    int n = blockIdx.x * 8 + (threadIdx.x >> 5);
    int lane = threadIdx.x & 31;
    float xs[8];
    ln_compute(n, lane, lw, lb, xs);
    size_t base = (size_t)n * FD + lane * 8;
    int j = lane * 8;
    float spv[8], mk[8], mr[8];
    ld8(sp + base, spv); ld8(tmk + j, mk); ld8(tmr + j, mr);
    float ok[8], orr[8];
#pragma unroll
    for (int t = 0; t < 8; t++) {
        ok[t]  = xs[t] * mk[t] + spv[t] * (1.f - mk[t]);
        orr[t] = xs[t] * mr[t] + spv[t] * (1.f - mr[t]);
    }
    st8(g_xk + base, ok); st8(g_xr + base, orr);
}

// ---------------- WKV single step + sigmoid gate ----------------
__global__ void wkv_kernel(const float* __restrict__ tf, const float* __restrict__ aa,
                           const float* __restrict__ bb, const float* __restrict__ pp) {
    size_t idx = (size_t)blockIdx.x * 256 + threadIdx.x;
    int c = threadIdx.x;
    float k = g_k[idx], v = g_v[idx], rpre = g_r[idx];
    float ww = tf[c] + k;
    float ppv = pp[idx];
    float p = fmaxf(ppv, ww);
    float e1 = expf(ppv - p), e2 = expf(ww - p);
    float wkv = (e1 * aa[idx] + e2 * v) / (e1 * bb[idx] + e2);
    float sig = 1.f / (1.f + expf(-rpre));
    g_xk[idx] = sig * wkv;  // reuse g_xk as gated value
}

// ---------------- depthwise 7x7 ----------------
__global__ void wt_transpose_kernel(const float* __restrict__ wt) {
    // wt[c*49 + t] -> g_wtT[t*256 + c]
    g_wtT[blockIdx.x * FD + threadIdx.x] = wt[threadIdx.x * 49 + blockIdx.x];
}

__global__ void dw7_kernel(const float* __restrict__ bias) {
    int n = blockIdx.x;
    int h = n / IMW, w = n % IMW;
    int c = threadIdx.x;
    float acc = bias[c];
#pragma unroll
    for (int u = 0; u < 7; u++) {
        int hh = h + u - 3;
        if (hh < 0 || hh >= IMH) continue;
#pragma unroll
        for (int vv = 0; vv < 7; vv++) {
            int ww2 = w + vv - 3;
            if (ww2 < 0 || ww2 >= IMW) continue;
            acc += g_d[((size_t)hh * IMW + ww2) * FD + c] * g_wtT[(u * 7 + vv) * FD + c];
        }
    }
    g_dw[(size_t)n * FD + c] = acc;
}

// ---------------- generic NT GEMM with fused epilogues ----------------
// C[M,Nout] = A[M,K] @ W[Nout,K]^T
// EPI 0: C=acc | 1: C=sigmoid(acc) | 2: C=relu(acc)^2
//     3: D+=acc | 4: D+=aux*acc | 5: D+=acc+bias[n]
template <int EPI>
__global__ __launch_bounds__(256)
void gemm_nt(const float* __restrict__ A, const float* __restrict__ Wm,
             float* __restrict__ C, float* __restrict__ D,
             const float* __restrict__ aux, const float* __restrict__ bias,
             int M, int Nout, int K) {
    __shared__ float As[16][64];
    __shared__ float Bs[16][64];
    const int tid = threadIdx.x;
    const int bm = blockIdx.y * 64;
    const int bn = blockIdx.x * 64;
    const int tx = tid & 15;
    const int ty = tid >> 4;
    const int lr = tid >> 2;
    const int lc = (tid & 3) * 4;
    const float* Ap = A + (size_t)(bm + lr) * K + lc;
    const float* Wp = Wm + (size_t)(bn + lr) * K + lc;
    float acc[4][4] = {};
    for (int k0 = 0; k0 < K; k0 += 16) {
        float4 a4 = *(const float4*)(Ap + k0);
        float4 w4 = *(const float4*)(Wp + k0);
        As[lc+0][lr] = a4.x; As[lc+1][lr] = a4.y; As[lc+2][lr] = a4.z; As[lc+3][lr] = a4.w;
        Bs[lc+0][lr] = w4.x; Bs[lc+1][lr] = w4.y; Bs[lc+2][lr] = w4.z; Bs[lc+3][lr] = w4.w;
        __syncthreads();
#pragma unroll
        for (int kk = 0; kk < 16; kk++) {
            float4 av = *(const float4*)&As[kk][ty * 4];
            float4 bv = *(const float4*)&Bs[kk][tx * 4];
            float am[4] = {av.x, av.y, av.z, av.w};
            float bm_[4] = {bv.x, bv.y, bv.z, bv.w};
#pragma unroll
            for (int i = 0; i < 4; i++)
#pragma unroll
                for (int j2 = 0; j2 < 4; j2++)
                    acc[i][j2] += am[i] * bm_[j2];
        }
        __syncthreads();
    }
#pragma unroll
    for (int i = 0; i < 4; i++) {
        int m = bm + ty * 4 + i;
        int n0 = bn + tx * 4;
        float4 r;
        r.x = acc[i][0]; r.y = acc[i][1]; r.z = acc[i][2]; r.w = acc[i][3];
        if (EPI == 0) {
            *(float4*)&C[(size_t)m * Nout + n0] = r;
        } else if (EPI == 1) {
            r.x = 1.f/(1.f+expf(-r.x)); r.y = 1.f/(1.f+expf(-r.y));
            r.z = 1.f/(1.f+expf(-r.z)); r.w = 1.f/(1.f+expf(-r.w));
            *(float4*)&C[(size_t)m * Nout + n0] = r;
        } else if (EPI == 2) {
            r.x = fmaxf(r.x, 0.f); r.x *= r.x;
            r.y = fmaxf(r.y, 0.f); r.y *= r.y;
            r.z = fmaxf(r.z, 0.f); r.z *= r.z;
            r.w = fmaxf(r.w, 0.f); r.w *= r.w;
            *(float4*)&C[(size_t)m * Nout + n0] = r;
        } else if (EPI == 3) {
            float4 dc = *(float4*)&D[(size_t)m * Nout + n0];
            dc.x += r.x; dc.y += r.y; dc.z += r.z; dc.w += r.w;
            *(float4*)&D[(size_t)m * Nout + n0] = dc;
        } else if (EPI == 4) {
            float4 av = *(const float4*)&aux[(size_t)m * Nout + n0];
            float4 dc = *(float4*)&D[(size_t)m * Nout + n0];
            dc.x += av.x * r.x; dc.y += av.y * r.y;
            dc.z += av.z * r.z; dc.w += av.w * r.w;
            *(float4*)&D[(size_t)m * Nout + n0] = dc;
        } else if (EPI == 5) {
            float4 bv = *(const float4*)&bias[n0];
            float4 dc = *(float4*)&D[(size_t)m * Nout + n0];
            dc.x += r.x + bv.x; dc.y += r.y + bv.y;
            dc.z += r.z + bv.z; dc.w += r.w + bv.w;
            *(float4*)&D[(size_t)m * Nout + n0] = dc;
        }
    }
}

// ---------------- output transpose [N,F] -> [F,N] ----------------
__global__ void out_transpose(float* __restrict__ out) {
    __shared__ float tile[32][33];
    int bn = blockIdx.x * 32;   // tokens
    int bc = blockIdx.y * 32;   // channels
    int tx = threadIdx.x, ty = threadIdx.y;
#pragma unroll
    for (int j = 0; j < 32; j += 8)
        tile[ty + j][tx] = g_d[(size_t)(bn + ty + j) * FD + bc + tx];
    __syncthreads();
#pragma unroll
    for (int j = 0; j < 32; j += 8)
        out[(size_t)(bc + ty + j) * NTOK + bn + tx] = tile[tx][ty + j];
}

// ---------------- host orchestration ----------------
extern "C" void kernel_launch(void* const* d_in, const int* in_sizes, int n_in,
                              void* d_out, int out_size) {
    auto IN = [&](int i) { return (const float*)d_in[i]; };
    // Fixed-position inputs
    const float* x    = IN(0);
    const float* cw1  = IN(1);
    const float* cb1  = IN(2);
    const float* cw2  = IN(3);
    const float* cb2  = IN(4);
    const float* ln0w = IN(5);
    const float* ln0b = IN(6);
    const float* ln1w = IN(7);
    const float* ln1b = IN(8);
    const float* ln2w = IN(9);
    const float* ln2b = IN(10);
    const float* atmk = IN(11);
    const float* atmv = IN(12);
    const float* atmr = IN(13);
    // Disambiguate metadata ordering: dict order has att_tf(1024) at 16,
    // signature order has att_kw(262144) at 16.
    bool sig = (in_sizes[16] > 2048);
    const float *atf, *akw, *avw, *arw, *aow, *ftmk, *ftmr, *fkw, *fvw, *frw;
    if (sig) {
        atf = IN(14);              /* atd = IN(15) unused */
        akw = IN(16); avw = IN(17); arw = IN(18); aow = IN(19);
        ftmk = IN(20); ftmr = IN(21);
        fkw = IN(22); fvw = IN(23); frw = IN(24);
    } else {
        ftmk = IN(14); ftmr = IN(15);
        atf = IN(16);              /* atd = IN(17) unused */
        akw = IN(18); avw = IN(19); arw = IN(20); aow = IN(21);
        frw = IN(22); fkw = IN(23); fvw = IN(24);
    }
    const float* sdww = IN(25);
    const float* sdwb = IN(26);
    const float* spww = IN(27);
    const float* spwb = IN(28);
    const float* st   = IN(29);

    float *pd, *pxk, *pxv, *pxr, *pk, *pv, *pr, *prr, *phid, *pdw;
    cudaGetSymbolAddress((void**)&pd,   g_d);
    cudaGetSymbolAddress((void**)&pxk,  g_xk);
    cudaGetSymbolAddress((void**)&pxv,  g_xv);
    cudaGetSymbolAddress((void**)&pxr,  g_xr);
    cudaGetSymbolAddress((void**)&pk,   g_k);
    cudaGetSymbolAddress((void**)&pv,   g_v);
    cudaGetSymbolAddress((void**)&pr,   g_r);
    cudaGetSymbolAddress((void**)&prr,  g_rr);
    cudaGetSymbolAddress((void**)&phid, g_hid);
    cudaGetSymbolAddress((void**)&pdw,  g_dw);

    stem_kernel<<<NTOK, 256>>>(x, cw1, cb1, cw2, cb2);

    const dim3 g256(FD / 64, NTOK / 64);
    const dim3 g1024(FHID / 64, NTOK / 64);
    const size_t NF = (size_t)NTOK * FD;

    for (int i = 0; i < NL; i++) {
        const float* sp0 = st + (size_t)(5 * i + 0) * NF;
        const float* sp1 = st + (size_t)(5 * i + 1) * NF;
        const float* aa  = st + (size_t)(5 * i + 2) * NF;
        const float* bb  = st + (size_t)(5 * i + 3) * NF;
        const float* pp  = st + (size_t)(5 * i + 4) * NF;

        if (i == 0)
            ln_plain_kernel<<<NTOK / 8, 256>>>(ln0w, ln0b);

        // --- attention (single-step WKV) ---
        ln_mix3_kernel<<<NTOK / 8, 256>>>(ln1w + i * FD, ln1b + i * FD,
                                          atmk + i * FD, atmv + i * FD, atmr + i * FD, sp1);
        gemm_nt<0><<<g256, 256>>>(pxk, akw + (size_t)i * FD * FD, pk, nullptr, nullptr, nullptr, NTOK, FD, FD);
        gemm_nt<0><<<g256, 256>>>(pxv, avw + (size_t)i * FD * FD, pv, nullptr, nullptr, nullptr, NTOK, FD, FD);
        gemm_nt<0><<<g256, 256>>>(pxr, arw + (size_t)i * FD * FD, pr, nullptr, nullptr, nullptr, NTOK, FD, FD);
        wkv_kernel<<<NTOK, 256>>>(atf + i * FD, aa, bb, pp);
        gemm_nt<3><<<g256, 256>>>(pxk, aow + (size_t)i * FD * FD, nullptr, pd, nullptr, nullptr, NTOK, FD, FD);

        // --- FFN (squared-relu channel mix) ---
        ln_mix2_kernel<<<NTOK / 8, 256>>>(ln2w + i * FD, ln2b + i * FD,
                                          ftmk + i * FD, ftmr + i * FD, sp0);
        gemm_nt<2><<<g1024, 256>>>(pxk, fkw + (size_t)i * FHID * FD, phid, nullptr, nullptr, nullptr, NTOK, FHID, FD);
        gemm_nt<1><<<g256, 256>>>(pxr, frw + (size_t)i * FD * FD, prr, nullptr, nullptr, nullptr, NTOK, FD, FD);
        gemm_nt<4><<<g256, 256>>>(phid, fvw + (size_t)i * FD * FHID, nullptr, pd, prr, nullptr, NTOK, FD, FHID);

        // --- spatial residual ---
        wt_transpose_kernel<<<49, 256>>>(sdww + (size_t)i * FD * 49);
        dw7_kernel<<<NTOK, 256>>>(sdwb + i * FD);
        gemm_nt<5><<<g256, 256>>>(pdw, spww + (size_t)i * FD * FD, nullptr, pd, nullptr, spwb + i * FD, NTOK, FD, FD);
    }

    out_transpose<<<dim3(NTOK / 32, FD / 32), dim3(32, 8)>>>((float*)d_out);
}

// round 2
// speedup vs baseline: 2.2163x; 2.2163x over previous
#include <cuda_runtime.h>
#include <cstdint>
#include <cstddef>

#define NTOK 25600
#define FD   256
#define FHID 1024
#define IMH  160
#define IMW  160
#define NL   4

// ---------------- scratch (device globals; no allocs allowed) ----------------
__device__ float g_d  [NTOK*FD];
__device__ float g_xk [NTOK*FD];
__device__ float g_xv [NTOK*FD];
__device__ float g_xr [NTOK*FD];
__device__ float g_k  [NTOK*FD];
__device__ float g_v  [NTOK*FD];
__device__ float g_r  [NTOK*FD];
__device__ float g_rr [NTOK*FD];
__device__ float g_hid[NTOK*FHID];
__device__ float g_dw [NTOK*FD];
__device__ float g_wtT[49*FD];

// ---------------- helpers ----------------
__device__ __forceinline__ float wsum(float v) {
#pragma unroll
    for (int o = 16; o; o >>= 1) v += __shfl_xor_sync(0xffffffffu, v, o);
    return v;
}

__device__ __forceinline__ void ld8(const float* __restrict__ p, float v[8]) {
    float4 a = *(const float4*)p;
    float4 b = *(const float4*)(p + 4);
    v[0]=a.x; v[1]=a.y; v[2]=a.z; v[3]=a.w; v[4]=b.x; v[5]=b.y; v[6]=b.z; v[7]=b.w;
}
__device__ __forceinline__ void st8(float* __restrict__ p, const float v[8]) {
    float4 a{v[0],v[1],v[2],v[3]}, b{v[4],v[5],v[6],v[7]};
    *(float4*)p = a; *(float4*)(p + 4) = b;
}

__device__ __forceinline__ uint32_t f2tf32(float f) {
    uint32_t u;
    asm("cvt.rna.tf32.f32 %0, %1;" : "=r"(u) : "f"(f));
    return u;
}

// LayerNorm over 256 features: one warp per token, 8 features per lane.
__device__ __forceinline__ void ln_compute(int n, int lane,
                                           const float* __restrict__ lw,
                                           const float* __restrict__ lb,
                                           float xs[8]) {
    const float* row = g_d + (size_t)n * FD + lane * 8;
    float v[8]; ld8(row, v);
    float s = v[0]+v[1]+v[2]+v[3]+v[4]+v[5]+v[6]+v[7];
    float mu = wsum(s) * (1.f / 256.f);
    float q = 0.f;
#pragma unroll
    for (int t = 0; t < 8; t++) { float dd = v[t] - mu; q += dd * dd; }
    float rs = rsqrtf(wsum(q) * (1.f / 256.f) + 1e-5f);
    float wv[8], bv[8];
    ld8(lw + lane*8, wv); ld8(lb + lane*8, bv);
#pragma unroll
    for (int t = 0; t < 8; t++) xs[t] = (v[t] - mu) * rs * wv[t] + bv[t];
}

// ---------------- stem: 1x1 conv (1->256) + depthwise 7x7 + WSiLU ----------------
__global__ void stem_kernel(const float* __restrict__ x,
                            const float* __restrict__ w1, const float* __restrict__ b1,
                            const float* __restrict__ w2, const float* __restrict__ b2) {
    int n = blockIdx.x;
    int h = n / IMW, w = n % IMW;
    int c = threadIdx.x;
    __shared__ float sx[49];
    __shared__ float sm[49];
    if (threadIdx.x < 49) {
        int u = threadIdx.x / 7, vv = threadIdx.x % 7;
        int hh = h + u - 3, ww = w + vv - 3;
        bool in = (hh >= 0 && hh < IMH && ww >= 0 && ww < IMW);
        sx[threadIdx.x] = in ? x[hh * IMW + ww] : 0.f;
        sm[threadIdx.x] = in ? 1.f : 0.f;
    }
    __syncthreads();
    float a = w1[c], bb = b1[c];
    float acc = b2[c];
#pragma unroll
    for (int t = 0; t < 49; t++)
        acc += (sx[t] * a + bb * sm[t]) * w2[c * 49 + t];
    float s = 1.f / (1.f + expf(-4.f * acc));
    g_d[(size_t)n * FD + c] = s * acc;
}

// ---------------- LN kernels ----------------
__global__ void ln_plain_kernel(const float* __restrict__ lw, const float* __restrict__ lb) {
    int n = blockIdx.x * 8 + (threadIdx.x >> 5);
    int lane = threadIdx.x & 31;
    float xs[8];
    ln_compute(n, lane, lw, lb, xs);
    st8(g_d + (size_t)n * FD + lane * 8, xs);
}

__global__ void ln_mix3_kernel(const float* __restrict__ lw, const float* __restrict__ lb,
                               const float* __restrict__ tmk, const float* __restrict__ tmv,
                               const float* __restrict__ tmr, const float* __restrict__ sp) {
    int n = blockIdx.x * 8 + (threadIdx.x >> 5);
    int lane = threadIdx.x & 31;
    float xs[8];
    ln_compute(n, lane, lw, lb, xs);
    size_t base = (size_t)n * FD + lane * 8;
    int j = lane * 8;
    float spv[8], mk[8], mv[8], mr[8];
    ld8(sp + base, spv); ld8(tmk + j, mk); ld8(tmv + j, mv); ld8(tmr + j, mr);
    float ok[8], ov[8], orr[8];
#pragma unroll
    for (int t = 0; t < 8; t++) {
        ok[t]  = xs[t] * mk[t] + spv[t] * (1.f - mk[t]);
        ov[t]  = xs[t] * mv[t] + spv[t] * (1.f - mv[t]);
        orr[t] = xs[t] * mr[t] + spv[t] * (1.f - mr[t]);
    }
    st8(g_xk + base, ok); st8(g_xv + base, ov); st8(g_xr + base, orr);
}

__global__ void ln_mix2_kernel(const float* __restrict__ lw, const float* __restrict__ lb,
                               const float* __restrict__ tmk, const float* __restrict__ tmr,
                               const float* __restrict__ sp) {
    int n = blockIdx.x * 8 + (threadIdx.x >> 5);
    int lane = threadIdx.x & 31;
    float xs[8];
    ln_compute(n, lane, lw, lb, xs);
    size_t base = (size_t)n * FD + lane * 8;
    int j = lane * 8;
    float spv[8], mk[8], mr[8];
    ld8(sp + base, spv); ld8(tmk + j, mk); ld8(tmr + j, mr);
    float ok[8], orr[8];
#pragma unroll
    for (int t = 0; t < 8; t++) {
        ok[t]  = xs[t] * mk[t] + spv[t] * (1.f - mk[t]);
        orr[t] = xs[t] * mr[t] + spv[t] * (1.f - mr[t]);
    }
    st8(g_xk + base, ok); st8(g_xr + base, orr);
}

// ---------------- WKV single step + sigmoid gate ----------------
__global__ void wkv_kernel(const float* __restrict__ tf, const float* __restrict__ aa,
                           const float* __restrict__ bb, const float* __restrict__ pp) {
    size_t idx = (size_t)blockIdx.x * 256 + threadIdx.x;
    int c = threadIdx.x;
    float k = g_k[idx], v = g_v[idx], rpre = g_r[idx];
    float ww = tf[c] + k;
    float ppv = pp[idx];
    float p = fmaxf(ppv, ww);
    float e1 = expf(ppv - p), e2 = expf(ww - p);
    float wkv = (e1 * aa[idx] + e2 * v) / (e1 * bb[idx] + e2);
    float sig = 1.f / (1.f + expf(-rpre));
    g_xk[idx] = sig * wkv;  // reuse g_xk as gated value
}

// ---------------- depthwise 7x7 ----------------
__global__ void wt_transpose_kernel(const float* __restrict__ wt) {
    g_wtT[blockIdx.x * FD + threadIdx.x] = wt[threadIdx.x * 49 + blockIdx.x];
}

__global__ void dw7_kernel(const float* __restrict__ bias) {
    int n = blockIdx.x;
    int h = n / IMW, w = n % IMW;
    int c = threadIdx.x;
    float acc = bias[c];
#pragma unroll
    for (int u = 0; u < 7; u++) {
        int hh = h + u - 3;
        if (hh < 0 || hh >= IMH) continue;
#pragma unroll
        for (int vv = 0; vv < 7; vv++) {
            int ww2 = w + vv - 3;
            if (ww2 < 0 || ww2 >= IMW) continue;
            acc += g_d[((size_t)hh * IMW + ww2) * FD + c] * g_wtT[(u * 7 + vv) * FD + c];
        }
    }
    g_dw[(size_t)n * FD + c] = acc;
}

// ---------------- TF32 tensor-core NT GEMM with fused epilogues ----------------
// C[M,Nout] = A[M,K] @ W[Nout,K]^T  via mma.sync.m16n8k8.tf32
// Block tile 128x128x32, 8 warps (2m x 4n), warp tile 64x32.
// EPI 0: C=acc | 1: C=sigmoid(acc) | 2: C=relu(acc)^2
//     3: D+=acc | 4: D+=aux*acc | 5: D+=acc+bias[n]
#define BM 128
#define BN 128
#define BK 32
#define LDS_K 36   // padded k-stride (conflict-free fragment loads)

__device__ __forceinline__ void mma_tf32(float c[4], const uint32_t a[4], const uint32_t b[2]) {
    asm volatile(
        "mma.sync.aligned.m16n8k8.row.col.f32.tf32.tf32.f32 "
        "{%0,%1,%2,%3}, {%4,%5,%6,%7}, {%8,%9}, {%0,%1,%2,%3};"
        : "+f"(c[0]), "+f"(c[1]), "+f"(c[2]), "+f"(c[3])
        : "r"(a[0]), "r"(a[1]), "r"(a[2]), "r"(a[3]), "r"(b[0]), "r"(b[1]));
}

template <int EPI>
__global__ __launch_bounds__(256)
void gemm_tf32(const float* __restrict__ A, const float* __restrict__ Wm,
               float* __restrict__ C, float* __restrict__ D,
               const float* __restrict__ aux, const float* __restrict__ bias,
               int M, int Nout, int K) {
    __shared__ uint32_t As[BM * LDS_K];
    __shared__ uint32_t Bs[BN * LDS_K];

    const int tid  = threadIdx.x;
    const int bm   = blockIdx.y * BM;
    const int bn   = blockIdx.x * BN;
    const int wid  = tid >> 5;
    const int lane = tid & 31;
    const int wm   = wid & 1;        // 2 warp-rows (m)
    const int wn   = wid >> 1;       // 4 warp-cols (n)
    const int g    = lane >> 2;      // group id 0..7
    const int tg   = lane & 3;       // thread-in-group 0..3

    // gmem load mapping: each thread loads 4x float4 per tile (A and B)
    const int lr = tid >> 3;          // 0..31 (row within 32-row pass)
    const int lc = (tid & 7) * 4;     // k offset 0..28

    float acc[4][4][4];
#pragma unroll
    for (int i = 0; i < 4; i++)
#pragma unroll
        for (int j = 0; j < 4; j++)
#pragma unroll
            for (int t = 0; t < 4; t++) acc[i][j][t] = 0.f;

    const int nk = K / BK;
    float4 ra[4], rb[4];

    // prologue loads (kt = 0)
#pragma unroll
    for (int p = 0; p < 4; p++) {
        ra[p] = *(const float4*)(A  + (size_t)(bm + lr + p * 32) * K + lc);
        rb[p] = *(const float4*)(Wm + (size_t)(bn + lr + p * 32) * K + lc);
    }

    for (int kt = 0; kt < nk; kt++) {
        __syncthreads();
        // store (with round-to-nearest tf32 conversion)
#pragma unroll
        for (int p = 0; p < 4; p++) {
            uint32_t* pa = &As[(lr + p * 32) * LDS_K + lc];
            pa[0] = f2tf32(ra[p].x); pa[1] = f2tf32(ra[p].y);
            pa[2] = f2tf32(ra[p].z); pa[3] = f2tf32(ra[p].w);
            uint32_t* pb = &Bs[(lr + p * 32) * LDS_K + lc];
            pb[0] = f2tf32(rb[p].x); pb[1] = f2tf32(rb[p].y);
            pb[2] = f2tf32(rb[p].z); pb[3] = f2tf32(rb[p].w);
        }
        __syncthreads();

        // prefetch next tile while computing
        if (kt + 1 < nk) {
            int k0 = (kt + 1) * BK;
#pragma unroll
            for (int p = 0; p < 4; p++) {
                ra[p] = *(const float4*)(A  + (size_t)(bm + lr + p * 32) * K + k0 + lc);
                rb[p] = *(const float4*)(Wm + (size_t)(bn + lr + p * 32) * K + k0 + lc);
            }
        }

#pragma unroll
        for (int kk = 0; kk < 4; kk++) {
            uint32_t af[4][4], bf[4][2];
#pragma unroll
            for (int mt = 0; mt < 4; mt++) {
                int row = wm * 64 + mt * 16;
                const uint32_t* base = &As[(row + g) * LDS_K + kk * 8 + tg];
                af[mt][0] = base[0];
                af[mt][1] = base[8 * LDS_K];
                af[mt][2] = base[4];
                af[mt][3] = base[8 * LDS_K + 4];
            }
#pragma unroll
            for (int nt = 0; nt < 4; nt++) {
                int col = wn * 32 + nt * 8;
                const uint32_t* base = &Bs[(col + g) * LDS_K + kk * 8 + tg];
                bf[nt][0] = base[0];
                bf[nt][1] = base[4];
            }
#pragma unroll
            for (int mt = 0; mt < 4; mt++)
#pragma unroll
                for (int nt = 0; nt < 4; nt++)
                    mma_tf32(acc[mt][nt], af[mt], bf[nt]);
        }
    }

    // epilogue: each frag writes 2x float2 (rows g and g+8)
#pragma unroll
    for (int mt = 0; mt < 4; mt++) {
#pragma unroll
        for (int nt = 0; nt < 4; nt++) {
            int row0 = bm + wm * 64 + mt * 16 + g;
            int col0 = bn + wn * 32 + nt * 8 + 2 * tg;
#pragma unroll
            for (int h = 0; h < 2; h++) {
                int row = row0 + h * 8;
                float2 r{acc[mt][nt][2 * h], acc[mt][nt][2 * h + 1]};
                size_t off = (size_t)row * Nout + col0;
                if (EPI == 0) {
                    *(float2*)&C[off] = r;
                } else if (EPI == 1) {
                    r.x = 1.f / (1.f + expf(-r.x));
                    r.y = 1.f / (1.f + expf(-r.y));
                    *(float2*)&C[off] = r;
                } else if (EPI == 2) {
                    r.x = fmaxf(r.x, 0.f); r.x *= r.x;
                    r.y = fmaxf(r.y, 0.f); r.y *= r.y;
                    *(float2*)&C[off] = r;
                } else if (EPI == 3) {
                    float2 dc = *(float2*)&D[off];
                    dc.x += r.x; dc.y += r.y;
                    *(float2*)&D[off] = dc;
                } else if (EPI == 4) {
                    float2 av = *(const float2*)&aux[off];
                    float2 dc = *(float2*)&D[off];
                    dc.x += av.x * r.x; dc.y += av.y * r.y;
                    *(float2*)&D[off] = dc;
                } else if (EPI == 5) {
                    float2 bv = *(const float2*)&bias[col0];
                    float2 dc = *(float2*)&D[off];
                    dc.x += r.x + bv.x; dc.y += r.y + bv.y;
                    *(float2*)&D[off] = dc;
                }
            }
        }
    }
}

// ---------------- output transpose [N,F] -> [F,N] ----------------
__global__ void out_transpose(float* __restrict__ out) {
    __shared__ float tile[32][33];
    int bn = blockIdx.x * 32;   // tokens
    int bc = blockIdx.y * 32;   // channels
    int tx = threadIdx.x, ty = threadIdx.y;
#pragma unroll
    for (int j = 0; j < 32; j += 8)
        tile[ty + j][tx] = g_d[(size_t)(bn + ty + j) * FD + bc + tx];
    __syncthreads();
#pragma unroll
    for (int j = 0; j < 32; j += 8)
        out[(size_t)(bc + ty + j) * NTOK + bn + tx] = tile[tx][ty + j];
}

// ---------------- host orchestration ----------------
extern "C" void kernel_launch(void* const* d_in, const int* in_sizes, int n_in,
                              void* d_out, int out_size) {
    auto IN = [&](int i) { return (const float*)d_in[i]; };
    const float* x    = IN(0);
    const float* cw1  = IN(1);
    const float* cb1  = IN(2);
    const float* cw2  = IN(3);
    const float* cb2  = IN(4);
    const float* ln0w = IN(5);
    const float* ln0b = IN(6);
    const float* ln1w = IN(7);
    const float* ln1b = IN(8);
    const float* ln2w = IN(9);
    const float* ln2b = IN(10);
    const float* atmk = IN(11);
    const float* atmv = IN(12);
    const float* atmr = IN(13);
    bool sig = (in_sizes[16] > 2048);
    const float *atf, *akw, *avw, *arw, *aow, *ftmk, *ftmr, *fkw, *fvw, *frw;
    if (sig) {
        atf = IN(14);
        akw = IN(16); avw = IN(17); arw = IN(18); aow = IN(19);
        ftmk = IN(20); ftmr = IN(21);
        fkw = IN(22); fvw = IN(23); frw = IN(24);
    } else {
        ftmk = IN(14); ftmr = IN(15);
        atf = IN(16);
        akw = IN(18); avw = IN(19); arw = IN(20); aow = IN(21);
        frw = IN(22); fkw = IN(23); fvw = IN(24);
    }
    const float* sdww = IN(25);
    const float* sdwb = IN(26);
    const float* spww = IN(27);
    const float* spwb = IN(28);
    const float* st   = IN(29);

    float *pd, *pxk, *pxv, *pxr, *pk, *pv, *pr, *prr, *phid, *pdw;
    cudaGetSymbolAddress((void**)&pd,   g_d);
    cudaGetSymbolAddress((void**)&pxk,  g_xk);
    cudaGetSymbolAddress((void**)&pxv,  g_xv);
    cudaGetSymbolAddress((void**)&pxr,  g_xr);
    cudaGetSymbolAddress((void**)&pk,   g_k);
    cudaGetSymbolAddress((void**)&pv,   g_v);
    cudaGetSymbolAddress((void**)&pr,   g_r);
    cudaGetSymbolAddress((void**)&prr,  g_rr);
    cudaGetSymbolAddress((void**)&phid, g_hid);
    cudaGetSymbolAddress((void**)&pdw,  g_dw);

    stem_kernel<<<NTOK, 256>>>(x, cw1, cb1, cw2, cb2);

    const dim3 g256(FD / BN, NTOK / BM);     // (2, 200)
    const dim3 g1024(FHID / BN, NTOK / BM);  // (8, 200)
    const size_t NF = (size_t)NTOK * FD;

    for (int i = 0; i < NL; i++) {
        const float* sp0 = st + (size_t)(5 * i + 0) * NF;
        const float* sp1 = st + (size_t)(5 * i + 1) * NF;
        const float* aa  = st + (size_t)(5 * i + 2) * NF;
        const float* bb  = st + (size_t)(5 * i + 3) * NF;
        const float* pp  = st + (size_t)(5 * i + 4) * NF;

        if (i == 0)
            ln_plain_kernel<<<NTOK / 8, 256>>>(ln0w, ln0b);

        // --- attention (single-step WKV) ---
        ln_mix3_kernel<<<NTOK / 8, 256>>>(ln1w + i * FD, ln1b + i * FD,
                                          atmk + i * FD, atmv + i * FD, atmr + i * FD, sp1);
        gemm_tf32<0><<<g256, 256>>>(pxk, akw + (size_t)i * FD * FD, pk, nullptr, nullptr, nullptr, NTOK, FD, FD);
        gemm_tf32<0><<<g256, 256>>>(pxv, avw + (size_t)i * FD * FD, pv, nullptr, nullptr, nullptr, NTOK, FD, FD);
        gemm_tf32<0><<<g256, 256>>>(pxr, arw + (size_t)i * FD * FD, pr, nullptr, nullptr, nullptr, NTOK, FD, FD);
        wkv_kernel<<<NTOK, 256>>>(atf + i * FD, aa, bb, pp);
        gemm_tf32<3><<<g256, 256>>>(pxk, aow + (size_t)i * FD * FD, nullptr, pd, nullptr, nullptr, NTOK, FD, FD);

        // --- FFN (squared-relu channel mix) ---
        ln_mix2_kernel<<<NTOK / 8, 256>>>(ln2w + i * FD, ln2b + i * FD,
                                          ftmk + i * FD, ftmr + i * FD, sp0);
        gemm_tf32<2><<<g1024, 256>>>(pxk, fkw + (size_t)i * FHID * FD, phid, nullptr, nullptr, nullptr, NTOK, FHID, FD);
        gemm_tf32<1><<<g256, 256>>>(pxr, frw + (size_t)i * FD * FD, prr, nullptr, nullptr, nullptr, NTOK, FD, FD);
        gemm_tf32<4><<<g256, 256>>>(phid, fvw + (size_t)i * FD * FHID, nullptr, pd, prr, nullptr, NTOK, FD, FHID);

        // --- spatial residual ---
        wt_transpose_kernel<<<49, 256>>>(sdww + (size_t)i * FD * 49);
        dw7_kernel<<<NTOK, 256>>>(sdwb + i * FD);
        gemm_tf32<5><<<g256, 256>>>(pdw, spww + (size_t)i * FD * FD, nullptr, pd, nullptr, spwb + i * FD, NTOK, FD, FD);
    }

    out_transpose<<<dim3(NTOK / 32, FD / 32), dim3(32, 8)>>>((float*)d_out);
}

// round 3
// speedup vs baseline: 2.4535x; 1.1070x over previous
#include <cuda_runtime.h>
#include <cstdint>
#include <cstddef>

#define NTOK 25600
#define FD   256
#define FHID 1024
#define IMH  160
#define IMW  160
#define NL   4

// ---------------- scratch (device globals; no allocs allowed) ----------------
__device__ float g_d  [NTOK*FD];
__device__ float g_xk [NTOK*FD];
__device__ float g_xv [NTOK*FD];
__device__ float g_xr [NTOK*FD];
__device__ float g_k  [NTOK*FD];
__device__ float g_v  [NTOK*FD];
__device__ float g_r  [NTOK*FD];
__device__ float g_rr [NTOK*FD];
__device__ float g_hid[NTOK*FHID];
__device__ float g_dw [NTOK*FD];
__device__ float g_wtT[49*FD];
__device__ float g_wbuf[3670016];   // tf32-rounded weights

// offsets (floats) into g_wbuf, each type contiguous over 4 layers
#define O_AKW 0
#define O_AVW 262144
#define O_ARW 524288
#define O_AOW 786432
#define O_FRW 1048576
#define O_SPW 1310720
#define O_FKW 1572864
#define O_FVW 2621440

// ---------------- helpers ----------------
__device__ __forceinline__ float wsum(float v) {
#pragma unroll
    for (int o = 16; o; o >>= 1) v += __shfl_xor_sync(0xffffffffu, v, o);
    return v;
}

__device__ __forceinline__ void ld8(const float* __restrict__ p, float v[8]) {
    float4 a = *(const float4*)p;
    float4 b = *(const float4*)(p + 4);
    v[0]=a.x; v[1]=a.y; v[2]=a.z; v[3]=a.w; v[4]=b.x; v[5]=b.y; v[6]=b.z; v[7]=b.w;
}
__device__ __forceinline__ void st8(float* __restrict__ p, const float v[8]) {
    float4 a{v[0],v[1],v[2],v[3]}, b{v[4],v[5],v[6],v[7]};
    *(float4*)p = a; *(float4*)(p + 4) = b;
}

__device__ __forceinline__ float rtf(float f) {   // round-to-nearest tf32
    uint32_t u;
    asm("cvt.rna.tf32.f32 %0, %1;" : "=r"(u) : "f"(f));
    return __uint_as_float(u);
}

// ---------------- weight tf32 pre-conversion ----------------
__global__ void cvt_tf32_kernel(const float* __restrict__ s, float* __restrict__ d, int n) {
    int i = (blockIdx.x * 256 + threadIdx.x) * 4;
    if (i < n) {
        float4 v = *(const float4*)(s + i);
        v.x = rtf(v.x); v.y = rtf(v.y); v.z = rtf(v.z); v.w = rtf(v.w);
        *(float4*)(d + i) = v;
    }
}

// LayerNorm over 256 features: one warp per token, 8 features per lane.
__device__ __forceinline__ void ln_compute(int n, int lane,
                                           const float* __restrict__ lw,
                                           const float* __restrict__ lb,
                                           float xs[8]) {
    const float* row = g_d + (size_t)n * FD + lane * 8;
    float v[8]; ld8(row, v);
    float s = v[0]+v[1]+v[2]+v[3]+v[4]+v[5]+v[6]+v[7];
    float mu = wsum(s) * (1.f / 256.f);
    float q = 0.f;
#pragma unroll
    for (int t = 0; t < 8; t++) { float dd = v[t] - mu; q += dd * dd; }
    float rs = rsqrtf(wsum(q) * (1.f / 256.f) + 1e-5f);
    float wv[8], bv[8];
    ld8(lw + lane*8, wv); ld8(lb + lane*8, bv);
#pragma unroll
    for (int t = 0; t < 8; t++) xs[t] = (v[t] - mu) * rs * wv[t] + bv[t];
}

// ---------------- stem ----------------
__global__ void stem_kernel(const float* __restrict__ x,
                            const float* __restrict__ w1, const float* __restrict__ b1,
                            const float* __restrict__ w2, const float* __restrict__ b2) {
    int n = blockIdx.x;
    int h = n / IMW, w = n % IMW;
    int c = threadIdx.x;
    __shared__ float sx[49];
    __shared__ float sm[49];
    if (threadIdx.x < 49) {
        int u = threadIdx.x / 7, vv = threadIdx.x % 7;
        int hh = h + u - 3, ww = w + vv - 3;
        bool in = (hh >= 0 && hh < IMH && ww >= 0 && ww < IMW);
        sx[threadIdx.x] = in ? x[hh * IMW + ww] : 0.f;
        sm[threadIdx.x] = in ? 1.f : 0.f;
    }
    __syncthreads();
    float a = w1[c], bb = b1[c];
    float acc = b2[c];
#pragma unroll
    for (int t = 0; t < 49; t++)
        acc += (sx[t] * a + bb * sm[t]) * w2[c * 49 + t];
    float s = 1.f / (1.f + expf(-4.f * acc));
    g_d[(size_t)n * FD + c] = s * acc;
}

// ---------------- LN kernels (outputs tf32-rounded where consumed by GEMM) ----------------
__global__ void ln_plain_kernel(const float* __restrict__ lw, const float* __restrict__ lb) {
    int n = blockIdx.x * 8 + (threadIdx.x >> 5);
    int lane = threadIdx.x & 31;
    float xs[8];
    ln_compute(n, lane, lw, lb, xs);
    st8(g_d + (size_t)n * FD + lane * 8, xs);
}

__global__ void ln_mix3_kernel(const float* __restrict__ lw, const float* __restrict__ lb,
                               const float* __restrict__ tmk, const float* __restrict__ tmv,
                               const float* __restrict__ tmr, const float* __restrict__ sp) {
    int n = blockIdx.x * 8 + (threadIdx.x >> 5);
    int lane = threadIdx.x & 31;
    float xs[8];
    ln_compute(n, lane, lw, lb, xs);
    size_t base = (size_t)n * FD + lane * 8;
    int j = lane * 8;
    float spv[8], mk[8], mv[8], mr[8];
    ld8(sp + base, spv); ld8(tmk + j, mk); ld8(tmv + j, mv); ld8(tmr + j, mr);
    float ok[8], ov[8], orr[8];
#pragma unroll
    for (int t = 0; t < 8; t++) {
        ok[t]  = rtf(xs[t] * mk[t] + spv[t] * (1.f - mk[t]));
        ov[t]  = rtf(xs[t] * mv[t] + spv[t] * (1.f - mv[t]));
        orr[t] = rtf(xs[t] * mr[t] + spv[t] * (1.f - mr[t]));
    }
    st8(g_xk + base, ok); st8(g_xv + base, ov); st8(g_xr + base, orr);
}

__global__ void ln_mix2_kernel(const float* __restrict__ lw, const float* __restrict__ lb,
                               const float* __restrict__ tmk, const float* __restrict__ tmr,
                               const float* __restrict__ sp) {
    int n = blockIdx.x * 8 + (threadIdx.x >> 5);
    int lane = threadIdx.x & 31;
    float xs[8];
    ln_compute(n, lane, lw, lb, xs);
    size_t base = (size_t)n * FD + lane * 8;
    int j = lane * 8;
    float spv[8], mk[8], mr[8];
    ld8(sp + base, spv); ld8(tmk + j, mk); ld8(tmr + j, mr);
    float ok[8], orr[8];
#pragma unroll
    for (int t = 0; t < 8; t++) {
        ok[t]  = rtf(xs[t] * mk[t] + spv[t] * (1.f - mk[t]));
        orr[t] = rtf(xs[t] * mr[t] + spv[t] * (1.f - mr[t]));
    }
    st8(g_xk + base, ok); st8(g_xr + base, orr);
}

// ---------------- WKV single step + sigmoid gate ----------------
__global__ void wkv_kernel(const float* __restrict__ tf, const float* __restrict__ aa,
                           const float* __restrict__ bb, const float* __restrict__ pp) {
    size_t idx = (size_t)blockIdx.x * 256 + threadIdx.x;
    int c = threadIdx.x;
    float k = g_k[idx], v = g_v[idx], rpre = g_r[idx];
    float ww = tf[c] + k;
    float ppv = pp[idx];
    float p = fmaxf(ppv, ww);
    float e1 = expf(ppv - p), e2 = expf(ww - p);
    float wkv = (e1 * aa[idx] + e2 * v) / (e1 * bb[idx] + e2);
    float sig = 1.f / (1.f + expf(-rpre));
    g_xk[idx] = rtf(sig * wkv);  // reuse g_xk as gated value (feeds ow GEMM)
}

// ---------------- depthwise 7x7 (tiled) ----------------
__global__ void wt_transpose_kernel(const float* __restrict__ wt) {
    g_wtT[blockIdx.x * FD + threadIdx.x] = wt[threadIdx.x * 49 + blockIdx.x];
}

__global__ __launch_bounds__(256)
void dw7t_kernel(const float* __restrict__ bias) {
    __shared__ float tile[22 * 22 * 16];   // input patch, [pos][ch]
    __shared__ float ws[49 * 16];          // weights [tap][ch]
    __shared__ float bs[16];
    const int w0 = blockIdx.x * 16, h0 = blockIdx.y * 16, cb = blockIdx.z * 16;
    const int tid = threadIdx.x;

    if (tid < 196) {
        int t = tid >> 2, c4 = (tid & 3) * 4;
        *(float4*)&ws[t * 16 + c4] = *(const float4*)&g_wtT[t * FD + cb + c4];
    }
    if (tid < 16) bs[tid] = bias[cb + tid];

    for (int idx = tid; idx < 22 * 22 * 4; idx += 256) {
        int pos = idx >> 2, c4 = (idx & 3) * 4;
        int ih = pos / 22, iw = pos % 22;
        int gh = h0 + ih - 3, gw = w0 + iw - 3;
        float4 v{0.f, 0.f, 0.f, 0.f};
        if (gh >= 0 && gh < IMH && gw >= 0 && gw < IMW)
            v = *(const float4*)&g_d[((size_t)gh * IMW + gw) * FD + cb + c4];
        *(float4*)&tile[pos * 16 + c4] = v;
    }
    __syncthreads();

    const int c4id = tid & 3;
    const int sbase = tid >> 2;   // 0..63
    float acc[4][4];
    float4 bv = *(const float4*)&bs[c4id * 4];
#pragma unroll
    for (int j = 0; j < 4; j++) { acc[j][0] = bv.x; acc[j][1] = bv.y; acc[j][2] = bv.z; acc[j][3] = bv.w; }

#pragma unroll
    for (int u = 0; u < 7; u++) {
#pragma unroll
        for (int v7 = 0; v7 < 7; v7++) {
            float4 wv = *(const float4*)&ws[(u * 7 + v7) * 16 + c4id * 4];
#pragma unroll
            for (int j = 0; j < 4; j++) {
                int s = sbase + 64 * j;
                int sy = s >> 4, sx = s & 15;
                float4 tv = *(const float4*)&tile[((sy + u) * 22 + (sx + v7)) * 16 + c4id * 4];
                acc[j][0] += tv.x * wv.x; acc[j][1] += tv.y * wv.y;
                acc[j][2] += tv.z * wv.z; acc[j][3] += tv.w * wv.w;
            }
        }
    }
#pragma unroll
    for (int j = 0; j < 4; j++) {
        int s = sbase + 64 * j;
        int sy = s >> 4, sx = s & 15;
        float4 r{rtf(acc[j][0]), rtf(acc[j][1]), rtf(acc[j][2]), rtf(acc[j][3])};
        *(float4*)&g_dw[((size_t)(h0 + sy) * IMW + (w0 + sx)) * FD + cb + c4id * 4] = r;
    }
}

// ---------------- TF32 tensor-core NT GEMM, cp.async double-buffered ----------------
// C[M,Nout] = A[M,K] @ W[Nout,K]^T ; operands are pre-rounded tf32 bit patterns.
// Block 128x128x16, 8 warps (2m x 4n), warp tile 64x32, 2-stage cp.async pipeline.
#define BM 128
#define BN 128
#define BK 16
#define SROW 20   // padded k-stride in words: (g*20+tg) mod 32 distinct for g<8,tg<4

__device__ __forceinline__ void mma_tf32(float c[4], const uint32_t a[4], const uint32_t b[2]) {
    asm volatile(
        "mma.sync.aligned.m16n8k8.row.col.f32.tf32.tf32.f32 "
        "{%0,%1,%2,%3}, {%4,%5,%6,%7}, {%8,%9}, {%0,%1,%2,%3};"
        : "+f"(c[0]), "+f"(c[1]), "+f"(c[2]), "+f"(c[3])
        : "r"(a[0]), "r"(a[1]), "r"(a[2]), "r"(a[3]), "r"(b[0]), "r"(b[1]));
}

__device__ __forceinline__ void cp16(float* smem, const float* g) {
    uint32_t s = (uint32_t)__cvta_generic_to_shared(smem);
    asm volatile("cp.async.cg.shared.global [%0], [%1], 16;" :: "r"(s), "l"(g));
}

template <int EPI>
__global__ __launch_bounds__(256, 2)
void gemm_tf32(const float* __restrict__ A, const float* __restrict__ Wm,
               float* __restrict__ C, float* __restrict__ D,
               const float* __restrict__ aux, const float* __restrict__ bias,
               int M, int Nout, int K) {
    __shared__ float As[2][BM * SROW];
    __shared__ float Bs[2][BN * SROW];

    const int tid  = threadIdx.x;
    const int bm   = blockIdx.y * BM;
    const int bn   = blockIdx.x * BN;
    const int wid  = tid >> 5;
    const int lane = tid & 31;
    const int wm   = wid & 1;
    const int wn   = wid >> 1;
    const int g    = lane >> 2;
    const int tg   = lane & 3;

    const int lrow = tid >> 1;            // 0..127
    const int lkc  = (tid & 1) * 8;       // 0 or 8

    const float* Ab = A  + (size_t)(bm + lrow) * K + lkc;
    const float* Bb = Wm + (size_t)(bn + lrow) * K + lkc;

    float acc[4][4][4];
#pragma unroll
    for (int i = 0; i < 4; i++)
#pragma unroll
        for (int j = 0; j < 4; j++)
#pragma unroll
            for (int t = 0; t < 4; t++) acc[i][j][t] = 0.f;

    const int nk = K / BK;

    // prologue: stage 0
    {
        float* pa = &As[0][lrow * SROW + lkc];
        float* pb = &Bs[0][lrow * SROW + lkc];
        cp16(pa, Ab); cp16(pa + 4, Ab + 4);
        cp16(pb, Bb); cp16(pb + 4, Bb + 4);
        asm volatile("cp.async.commit_group;");
    }

    for (int kt = 0; kt < nk; kt++) {
        if (kt + 1 < nk) {
            int st = (kt + 1) & 1;
            const float* ga = Ab + (kt + 1) * BK;
            const float* gb = Bb + (kt + 1) * BK;
            float* pa = &As[st][lrow * SROW + lkc];
            float* pb = &Bs[st][lrow * SROW + lkc];
            cp16(pa, ga); cp16(pa + 4, ga + 4);
            cp16(pb, gb); cp16(pb + 4, gb + 4);
            asm volatile("cp.async.commit_group;");
            asm volatile("cp.async.wait_group 1;");
        } else {
            asm volatile("cp.async.wait_group 0;");
        }
        __syncthreads();

        const float* as = As[kt & 1];
        const float* bs = Bs[kt & 1];
#pragma unroll
        for (int kk = 0; kk < 2; kk++) {
            uint32_t af[4][4], bf[4][2];
#pragma unroll
            for (int mt = 0; mt < 4; mt++) {
                const float* base = &as[(wm * 64 + mt * 16 + g) * SROW + kk * 8 + tg];
                af[mt][0] = __float_as_uint(base[0]);
                af[mt][1] = __float_as_uint(base[8 * SROW]);
                af[mt][2] = __float_as_uint(base[4]);
                af[mt][3] = __float_as_uint(base[8 * SROW + 4]);
            }
#pragma unroll
            for (int nt = 0; nt < 4; nt++) {
                const float* base = &bs[(wn * 32 + nt * 8 + g) * SROW + kk * 8 + tg];
                bf[nt][0] = __float_as_uint(base[0]);
                bf[nt][1] = __float_as_uint(base[4]);
            }
#pragma unroll
            for (int mt = 0; mt < 4; mt++)
#pragma unroll
                for (int nt = 0; nt < 4; nt++)
                    mma_tf32(acc[mt][nt], af[mt], bf[nt]);
        }
        __syncthreads();
    }

    // epilogue
#pragma unroll
    for (int mt = 0; mt < 4; mt++) {
#pragma unroll
        for (int nt = 0; nt < 4; nt++) {
            int row0 = bm + wm * 64 + mt * 16 + g;
            int col0 = bn + wn * 32 + nt * 8 + 2 * tg;
#pragma unroll
            for (int h = 0; h < 2; h++) {
                int row = row0 + h * 8;
                float2 r{acc[mt][nt][2 * h], acc[mt][nt][2 * h + 1]};
                size_t off = (size_t)row * Nout + col0;
                if (EPI == 0) {
                    *(float2*)&C[off] = r;
                } else if (EPI == 1) {
                    r.x = 1.f / (1.f + expf(-r.x));
                    r.y = 1.f / (1.f + expf(-r.y));
                    *(float2*)&C[off] = r;
                } else if (EPI == 2) {
                    r.x = fmaxf(r.x, 0.f); r.x = rtf(r.x * r.x);
                    r.y = fmaxf(r.y, 0.f); r.y = rtf(r.y * r.y);
                    *(float2*)&C[off] = r;
                } else if (EPI == 3) {
                    float2 dc = *(float2*)&D[off];
                    dc.x += r.x; dc.y += r.y;
                    *(float2*)&D[off] = dc;
                } else if (EPI == 4) {
                    float2 av = *(const float2*)&aux[off];
                    float2 dc = *(float2*)&D[off];
                    dc.x += av.x * r.x; dc.y += av.y * r.y;
                    *(float2*)&D[off] = dc;
                } else if (EPI == 5) {
                    float2 bv = *(const float2*)&bias[col0];
                    float2 dc = *(float2*)&D[off];
                    dc.x += r.x + bv.x; dc.y += r.y + bv.y;
                    *(float2*)&D[off] = dc;
                }
            }
        }
    }
}

// ---------------- output transpose [N,F] -> [F,N] ----------------
__global__ void out_transpose(float* __restrict__ out) {
    __shared__ float tile[32][33];
    int bn = blockIdx.x * 32;
    int bc = blockIdx.y * 32;
    int tx = threadIdx.x, ty = threadIdx.y;
#pragma unroll
    for (int j = 0; j < 32; j += 8)
        tile[ty + j][tx] = g_d[(size_t)(bn + ty + j) * FD + bc + tx];
    __syncthreads();
#pragma unroll
    for (int j = 0; j < 32; j += 8)
        out[(size_t)(bc + ty + j) * NTOK + bn + tx] = tile[tx][ty + j];
}

// ---------------- host orchestration ----------------
extern "C" void kernel_launch(void* const* d_in, const int* in_sizes, int n_in,
                              void* d_out, int out_size) {
    auto IN = [&](int i) { return (const float*)d_in[i]; };
    const float* x    = IN(0);
    const float* cw1  = IN(1);
    const float* cb1  = IN(2);
    const float* cw2  = IN(3);
    const float* cb2  = IN(4);
    const float* ln0w = IN(5);
    const float* ln0b = IN(6);
    const float* ln1w = IN(7);
    const float* ln1b = IN(8);
    const float* ln2w = IN(9);
    const float* ln2b = IN(10);
    const float* atmk = IN(11);
    const float* atmv = IN(12);
    const float* atmr = IN(13);
    bool sig = (in_sizes[16] > 2048);
    const float *atf, *akw, *avw, *arw, *aow, *ftmk, *ftmr, *fkw, *fvw, *frw;
    if (sig) {
        atf = IN(14);
        akw = IN(16); avw = IN(17); arw = IN(18); aow = IN(19);
        ftmk = IN(20); ftmr = IN(21);
        fkw = IN(22); fvw = IN(23); frw = IN(24);
    } else {
        ftmk = IN(14); ftmr = IN(15);
        atf = IN(16);
        akw = IN(18); avw = IN(19); arw = IN(20); aow = IN(21);
        frw = IN(22); fkw = IN(23); fvw = IN(24);
    }
    const float* sdww = IN(25);
    const float* sdwb = IN(26);
    const float* spww = IN(27);
    const float* spwb = IN(28);
    const float* st   = IN(29);

    float *pd, *pxk, *pxv, *pxr, *pk, *pv, *pr, *prr, *phid, *pdw, *pw;
    cudaGetSymbolAddress((void**)&pd,   g_d);
    cudaGetSymbolAddress((void**)&pxk,  g_xk);
    cudaGetSymbolAddress((void**)&pxv,  g_xv);
    cudaGetSymbolAddress((void**)&pxr,  g_xr);
    cudaGetSymbolAddress((void**)&pk,   g_k);
    cudaGetSymbolAddress((void**)&pv,   g_v);
    cudaGetSymbolAddress((void**)&pr,   g_r);
    cudaGetSymbolAddress((void**)&prr,  g_rr);
    cudaGetSymbolAddress((void**)&phid, g_hid);
    cudaGetSymbolAddress((void**)&pdw,  g_dw);
    cudaGetSymbolAddress((void**)&pw,   g_wbuf);

    // weight pre-conversion (tf32 rounding), one launch per tensor type
    cvt_tf32_kernel<<<256, 256>>>(akw, pw + O_AKW, NL * FD * FD);
    cvt_tf32_kernel<<<256, 256>>>(avw, pw + O_AVW, NL * FD * FD);
    cvt_tf32_kernel<<<256, 256>>>(arw, pw + O_ARW, NL * FD * FD);
    cvt_tf32_kernel<<<256, 256>>>(aow, pw + O_AOW, NL * FD * FD);
    cvt_tf32_kernel<<<256, 256>>>(frw, pw + O_FRW, NL * FD * FD);
    cvt_tf32_kernel<<<256, 256>>>(spww, pw + O_SPW, NL * FD * FD);
    cvt_tf32_kernel<<<1024, 256>>>(fkw, pw + O_FKW, NL * FHID * FD);
    cvt_tf32_kernel<<<1024, 256>>>(fvw, pw + O_FVW, NL * FD * FHID);

    stem_kernel<<<NTOK, 256>>>(x, cw1, cb1, cw2, cb2);

    const dim3 g256(FD / BN, NTOK / BM);     // (2, 200)
    const dim3 g1024(FHID / BN, NTOK / BM);  // (8, 200)
    const dim3 gdw(IMW / 16, IMH / 16, FD / 16);
    const size_t NF = (size_t)NTOK * FD;

    for (int i = 0; i < NL; i++) {
        const float* sp0 = st + (size_t)(5 * i + 0) * NF;
        const float* sp1 = st + (size_t)(5 * i + 1) * NF;
        const float* aa  = st + (size_t)(5 * i + 2) * NF;
        const float* bb  = st + (size_t)(5 * i + 3) * NF;
        const float* pp  = st + (size_t)(5 * i + 4) * NF;
        const size_t wo256 = (size_t)i * FD * FD;
        const size_t wo1k  = (size_t)i * FHID * FD;

        if (i == 0)
            ln_plain_kernel<<<NTOK / 8, 256>>>(ln0w, ln0b);

        // --- attention (single-step WKV) ---
        ln_mix3_kernel<<<NTOK / 8, 256>>>(ln1w + i * FD, ln1b + i * FD,
                                          atmk + i * FD, atmv + i * FD, atmr + i * FD, sp1);
        gemm_tf32<0><<<g256, 256>>>(pxk, pw + O_AKW + wo256, pk, nullptr, nullptr, nullptr, NTOK, FD, FD);
        gemm_tf32<0><<<g256, 256>>>(pxv, pw + O_AVW + wo256, pv, nullptr, nullptr, nullptr, NTOK, FD, FD);
        gemm_tf32<0><<<g256, 256>>>(pxr, pw + O_ARW + wo256, pr, nullptr, nullptr, nullptr, NTOK, FD, FD);
        wkv_kernel<<<NTOK, 256>>>(atf + i * FD, aa, bb, pp);
        gemm_tf32<3><<<g256, 256>>>(pxk, pw + O_AOW + wo256, nullptr, pd, nullptr, nullptr, NTOK, FD, FD);

        // --- FFN (squared-relu channel mix) ---
        ln_mix2_kernel<<<NTOK / 8, 256>>>(ln2w + i * FD, ln2b + i * FD,
                                          ftmk + i * FD, ftmr + i * FD, sp0);
        gemm_tf32<2><<<g1024, 256>>>(pxk, pw + O_FKW + wo1k, phid, nullptr, nullptr, nullptr, NTOK, FHID, FD);
        gemm_tf32<1><<<g256, 256>>>(pxr, pw + O_FRW + wo256, prr, nullptr, nullptr, nullptr, NTOK, FD, FD);
        gemm_tf32<4><<<g256, 256>>>(phid, pw + O_FVW + wo1k, nullptr, pd, prr, nullptr, NTOK, FD, FHID);

        // --- spatial residual ---
        wt_transpose_kernel<<<49, 256>>>(sdww + (size_t)i * FD * 49);
        dw7t_kernel<<<gdw, 256>>>(sdwb + i * FD);
        gemm_tf32<5><<<g256, 256>>>(pdw, pw + O_SPW + wo256, nullptr, pd, nullptr, spwb + i * FD, NTOK, FD, FD);
    }

    out_transpose<<<dim3(NTOK / 32, FD / 32), dim3(32, 8)>>>((float*)d_out);
}

// round 4
// speedup vs baseline: 2.5216x; 1.0278x over previous
#include <cuda_runtime.h>
#include <cstdint>
#include <cstddef>

#define NTOK 25600
#define FD   256
#define FHID 1024
#define IMH  160
#define IMW  160
#define NL   4

// ---------------- scratch (device globals; no allocs allowed) ----------------
__device__ float g_d  [NTOK*FD];
__device__ float g_xk [NTOK*FD];
__device__ float g_xv [NTOK*FD];
__device__ float g_xr [NTOK*FD];
__device__ float g_k  [NTOK*FD];
__device__ float g_v  [NTOK*FD];
__device__ float g_r  [NTOK*FD];
__device__ float g_rr [NTOK*FD];
__device__ float g_hid[NTOK*FHID];
__device__ float g_dw [NTOK*FD];
__device__ float g_wtT[NL*49*FD];
__device__ float g_wbuf[3670016];   // tf32-rounded weights

// offsets (floats) into g_wbuf
#define O_AKW 0
#define O_AVW 262144
#define O_ARW 524288
#define O_AOW 786432
#define O_FRW 1048576
#define O_SPW 1310720
#define O_FKW 1572864
#define O_FVW 2621440

// ---------------- helpers ----------------
__device__ __forceinline__ float wsum(float v) {
#pragma unroll
    for (int o = 16; o; o >>= 1) v += __shfl_xor_sync(0xffffffffu, v, o);
    return v;
}

__device__ __forceinline__ void ld8(const float* __restrict__ p, float v[8]) {
    float4 a = *(const float4*)p;
    float4 b = *(const float4*)(p + 4);
    v[0]=a.x; v[1]=a.y; v[2]=a.z; v[3]=a.w; v[4]=b.x; v[5]=b.y; v[6]=b.z; v[7]=b.w;
}
__device__ __forceinline__ void st8(float* __restrict__ p, const float v[8]) {
    float4 a{v[0],v[1],v[2],v[3]}, b{v[4],v[5],v[6],v[7]};
    *(float4*)p = a; *(float4*)(p + 4) = b;
}

__device__ __forceinline__ float rtf(float f) {   // round-to-nearest tf32
    uint32_t u;
    asm("cvt.rna.tf32.f32 %0, %1;" : "=r"(u) : "f"(f));
    return __uint_as_float(u);
}

// ---------------- weight tf32 pre-conversion ----------------
__global__ void cvt_tf32_kernel(const float* __restrict__ s, float* __restrict__ d, int n) {
    int i = (blockIdx.x * 256 + threadIdx.x) * 4;
    if (i < n) {
        float4 v = *(const float4*)(s + i);
        v.x = rtf(v.x); v.y = rtf(v.y); v.z = rtf(v.z); v.w = rtf(v.w);
        *(float4*)(d + i) = v;
    }
}

// LayerNorm over 256 features: one warp per token, 8 features per lane (input from g_d).
__device__ __forceinline__ void ln_compute(int n, int lane,
                                           const float* __restrict__ lw,
                                           const float* __restrict__ lb,
                                           float xs[8]) {
    const float* row = g_d + (size_t)n * FD + lane * 8;
    float v[8]; ld8(row, v);
    float s = v[0]+v[1]+v[2]+v[3]+v[4]+v[5]+v[6]+v[7];
    float mu = wsum(s) * (1.f / 256.f);
    float q = 0.f;
#pragma unroll
    for (int t = 0; t < 8; t++) { float dd = v[t] - mu; q += dd * dd; }
    float rs = rsqrtf(wsum(q) * (1.f / 256.f) + 1e-5f);
    float wv[8], bv[8];
    ld8(lw + lane*8, wv); ld8(lb + lane*8, bv);
#pragma unroll
    for (int t = 0; t < 8; t++) xs[t] = (v[t] - mu) * rs * wv[t] + bv[t];
}

// LN on register values
__device__ __forceinline__ void ln_regs(const float in[8], int lane,
                                        const float* __restrict__ lw,
                                        const float* __restrict__ lb,
                                        float xs[8]) {
    float s = in[0]+in[1]+in[2]+in[3]+in[4]+in[5]+in[6]+in[7];
    float mu = wsum(s) * (1.f / 256.f);
    float q = 0.f;
#pragma unroll
    for (int t = 0; t < 8; t++) { float dd = in[t] - mu; q += dd * dd; }
    float rs = rsqrtf(wsum(q) * (1.f / 256.f) + 1e-5f);
    float wv[8], bv[8];
    ld8(lw + lane*8, wv); ld8(lb + lane*8, bv);
#pragma unroll
    for (int t = 0; t < 8; t++) xs[t] = (in[t] - mu) * rs * wv[t] + bv[t];
}

// ---------------- stem ----------------
__global__ void stem_kernel(const float* __restrict__ x,
                            const float* __restrict__ w1, const float* __restrict__ b1,
                            const float* __restrict__ w2, const float* __restrict__ b2) {
    int n = blockIdx.x;
    int h = n / IMW, w = n % IMW;
    int c = threadIdx.x;
    __shared__ float sx[49];
    __shared__ float sm[49];
    if (threadIdx.x < 49) {
        int u = threadIdx.x / 7, vv = threadIdx.x % 7;
        int hh = h + u - 3, ww = w + vv - 3;
        bool in = (hh >= 0 && hh < IMH && ww >= 0 && ww < IMW);
        sx[threadIdx.x] = in ? x[hh * IMW + ww] : 0.f;
        sm[threadIdx.x] = in ? 1.f : 0.f;
    }
    __syncthreads();
    float a = w1[c], bb = b1[c];
    float acc = b2[c];
#pragma unroll
    for (int t = 0; t < 49; t++)
        acc += (sx[t] * a + bb * sm[t]) * w2[c * 49 + t];
    float s = 1.f / (1.f + expf(-4.f * acc));
    g_d[(size_t)n * FD + c] = s * acc;
}

// ---------------- LN + mix kernels ----------------
__device__ __forceinline__ void mix3_store(const float xs[8], int lane, size_t base,
                                           const float* __restrict__ tmk,
                                           const float* __restrict__ tmv,
                                           const float* __restrict__ tmr,
                                           const float* __restrict__ sp) {
    int j = lane * 8;
    float spv[8], mk[8], mv[8], mr[8];
    ld8(sp + base, spv); ld8(tmk + j, mk); ld8(tmv + j, mv); ld8(tmr + j, mr);
    float ok[8], ov[8], orr[8];
#pragma unroll
    for (int t = 0; t < 8; t++) {
        ok[t]  = rtf(xs[t] * mk[t] + spv[t] * (1.f - mk[t]));
        ov[t]  = rtf(xs[t] * mv[t] + spv[t] * (1.f - mv[t]));
        orr[t] = rtf(xs[t] * mr[t] + spv[t] * (1.f - mr[t]));
    }
    st8(g_xk + base, ok); st8(g_xv + base, ov); st8(g_xr + base, orr);
}

__global__ void ln_mix3_kernel(const float* __restrict__ lw, const float* __restrict__ lb,
                               const float* __restrict__ tmk, const float* __restrict__ tmv,
                               const float* __restrict__ tmr, const float* __restrict__ sp) {
    int n = blockIdx.x * 8 + (threadIdx.x >> 5);
    int lane = threadIdx.x & 31;
    float xs[8];
    ln_compute(n, lane, lw, lb, xs);
    mix3_store(xs, lane, (size_t)n * FD + lane * 8, tmk, tmv, tmr, sp);
}

// layer0: ln0 applied to d (stored back), then ln1+mix in registers
__global__ void ln_first_mix3_kernel(const float* __restrict__ l0w, const float* __restrict__ l0b,
                                     const float* __restrict__ lw, const float* __restrict__ lb,
                                     const float* __restrict__ tmk, const float* __restrict__ tmv,
                                     const float* __restrict__ tmr, const float* __restrict__ sp) {
    int n = blockIdx.x * 8 + (threadIdx.x >> 5);
    int lane = threadIdx.x & 31;
    float xs0[8];
    ln_compute(n, lane, l0w, l0b, xs0);
    size_t base = (size_t)n * FD + lane * 8;
    st8(g_d + base, xs0);
    float xs[8];
    ln_regs(xs0, lane, lw, lb, xs);
    mix3_store(xs, lane, base, tmk, tmv, tmr, sp);
}

__global__ void ln_mix2_kernel(const float* __restrict__ lw, const float* __restrict__ lb,
                               const float* __restrict__ tmk, const float* __restrict__ tmr,
                               const float* __restrict__ sp) {
    int n = blockIdx.x * 8 + (threadIdx.x >> 5);
    int lane = threadIdx.x & 31;
    float xs[8];
    ln_compute(n, lane, lw, lb, xs);
    size_t base = (size_t)n * FD + lane * 8;
    int j = lane * 8;
    float spv[8], mk[8], mr[8];
    ld8(sp + base, spv); ld8(tmk + j, mk); ld8(tmr + j, mr);
    float ok[8], orr[8];
#pragma unroll
    for (int t = 0; t < 8; t++) {
        ok[t]  = rtf(xs[t] * mk[t] + spv[t] * (1.f - mk[t]));
        orr[t] = rtf(xs[t] * mr[t] + spv[t] * (1.f - mr[t]));
    }
    st8(g_xk + base, ok); st8(g_xr + base, orr);
}

// ---------------- WKV single step + sigmoid gate ----------------
__global__ void wkv_kernel(const float* __restrict__ tf, const float* __restrict__ aa,
                           const float* __restrict__ bb, const float* __restrict__ pp) {
    size_t idx = (size_t)blockIdx.x * 256 + threadIdx.x;
    int c = threadIdx.x;
    float k = g_k[idx], v = g_v[idx], rpre = g_r[idx];
    float ww = tf[c] + k;
    float ppv = pp[idx];
    float p = fmaxf(ppv, ww);
    float e1 = expf(ppv - p), e2 = expf(ww - p);
    float wkv = (e1 * aa[idx] + e2 * v) / (e1 * bb[idx] + e2);
    float sig = 1.f / (1.f + expf(-rpre));
    g_xk[idx] = rtf(sig * wkv);  // reuse g_xk as gated value (feeds ow GEMM)
}

// ---------------- depthwise 7x7 ----------------
__global__ void wt_all_kernel(const float* __restrict__ wt) {
    // wt[l][c][tap] -> g_wtT[l][tap][c]
    int l = blockIdx.y, tap = blockIdx.x, c = threadIdx.x;
    g_wtT[(l * 49 + tap) * FD + c] = wt[(l * FD + c) * 49 + tap];
}

__global__ __launch_bounds__(256)
void dw7t_kernel(const float* __restrict__ bias, const float* __restrict__ wtT) {
    __shared__ float tile[22 * 22 * 16];   // input patch, [pos][ch]
    __shared__ float ws[49 * 16];          // weights [tap][ch]
    __shared__ float bs[16];
    const int w0 = blockIdx.x * 16, h0 = blockIdx.y * 16, cb = blockIdx.z * 16;
    const int tid = threadIdx.x;

    if (tid < 196) {
        int t = tid >> 2, c4 = (tid & 3) * 4;
        *(float4*)&ws[t * 16 + c4] = *(const float4*)&wtT[t * FD + cb + c4];
    }
    if (tid < 16) bs[tid] = bias[cb + tid];

    for (int idx = tid; idx < 22 * 22 * 4; idx += 256) {
        int pos = idx >> 2, c4 = (idx & 3) * 4;
        int ih = pos / 22, iw = pos % 22;
        int gh = h0 + ih - 3, gw = w0 + iw - 3;
        float4 v{0.f, 0.f, 0.f, 0.f};
        if (gh >= 0 && gh < IMH && gw >= 0 && gw < IMW)
            v = *(const float4*)&g_d[((size_t)gh * IMW + gw) * FD + cb + c4];
        *(float4*)&tile[pos * 16 + c4] = v;
    }
    __syncthreads();

    const int c4id = tid & 3;
    const int sbase = tid >> 2;   // 0..63
    float acc[4][4];
    float4 bv = *(const float4*)&bs[c4id * 4];
#pragma unroll
    for (int j = 0; j < 4; j++) { acc[j][0] = bv.x; acc[j][1] = bv.y; acc[j][2] = bv.z; acc[j][3] = bv.w; }

#pragma unroll
    for (int u = 0; u < 7; u++) {
#pragma unroll
        for (int v7 = 0; v7 < 7; v7++) {
            float4 wv = *(const float4*)&ws[(u * 7 + v7) * 16 + c4id * 4];
#pragma unroll
            for (int j = 0; j < 4; j++) {
                int s = sbase + 64 * j;
                int sy = s >> 4, sx = s & 15;
                float4 tv = *(const float4*)&tile[((sy + u) * 22 + (sx + v7)) * 16 + c4id * 4];
                acc[j][0] += tv.x * wv.x; acc[j][1] += tv.y * wv.y;
                acc[j][2] += tv.z * wv.z; acc[j][3] += tv.w * wv.w;
            }
        }
    }
#pragma unroll
    for (int j = 0; j < 4; j++) {
        int s = sbase + 64 * j;
        int sy = s >> 4, sx = s & 15;
        float4 r{rtf(acc[j][0]), rtf(acc[j][1]), rtf(acc[j][2]), rtf(acc[j][3])};
        *(float4*)&g_dw[((size_t)(h0 + sy) * IMW + (w0 + sx)) * FD + cb + c4id * 4] = r;
    }
}

// ---------------- TF32 tensor-core NT GEMM, 3-stage cp.async, 1 sync/iter ----------------
#define BM 128
#define BN 128
#define BK 16
#define SROW 20                     // padded k-stride in words
#define SSTRIDE ((BM + BN) * SROW)  // floats per stage (5120)
#define GSMEM (3 * SSTRIDE * 4)     // dynamic smem bytes (61440)

__device__ __forceinline__ void mma_tf32(float c[4], const uint32_t a[4], const uint32_t b[2]) {
    asm volatile(
        "mma.sync.aligned.m16n8k8.row.col.f32.tf32.tf32.f32 "
        "{%0,%1,%2,%3}, {%4,%5,%6,%7}, {%8,%9}, {%0,%1,%2,%3};"
        : "+f"(c[0]), "+f"(c[1]), "+f"(c[2]), "+f"(c[3])
        : "r"(a[0]), "r"(a[1]), "r"(a[2]), "r"(a[3]), "r"(b[0]), "r"(b[1]));
}

__device__ __forceinline__ void cp16(float* smem, const float* g) {
    uint32_t s = (uint32_t)__cvta_generic_to_shared(smem);
    asm volatile("cp.async.cg.shared.global [%0], [%1], 16;" :: "r"(s), "l"(g));
}

template <int EPI>
__global__ __launch_bounds__(256, 2)
void gemm_tf32(const float* __restrict__ A, const float* __restrict__ Wm,
               float* __restrict__ C, float* __restrict__ D,
               const float* __restrict__ aux, const float* __restrict__ bias,
               int M, int Nout, int K) {
    extern __shared__ float smem[];

    const int tid  = threadIdx.x;
    const int bm   = blockIdx.y * BM;
    const int bn   = blockIdx.x * BN;
    const int wid  = tid >> 5;
    const int lane = tid & 31;
    const int wm   = wid & 1;
    const int wn   = wid >> 1;
    const int g    = lane >> 2;
    const int tg   = lane & 3;

    const int lrow = tid >> 1;            // 0..127
    const int lkc  = (tid & 1) * 8;       // 0 or 8

    const float* Ab = A  + (size_t)(bm + lrow) * K + lkc;
    const float* Bb = Wm + (size_t)(bn + lrow) * K + lkc;
    float* const sA = smem + lrow * SROW + lkc;
    float* const sB = smem + BM * SROW + lrow * SROW + lkc;

    float acc[4][4][4];
#pragma unroll
    for (int i = 0; i < 4; i++)
#pragma unroll
        for (int j = 0; j < 4; j++)
#pragma unroll
            for (int t = 0; t < 4; t++) acc[i][j][t] = 0.f;

    const int nk = K / BK;

    // prologue: stages 0 and 1
    {
        cp16(sA, Ab); cp16(sA + 4, Ab + 4);
        cp16(sB, Bb); cp16(sB + 4, Bb + 4);
        asm volatile("cp.async.commit_group;");
        cp16(sA + SSTRIDE, Ab + BK); cp16(sA + SSTRIDE + 4, Ab + BK + 4);
        cp16(sB + SSTRIDE, Bb + BK); cp16(sB + SSTRIDE + 4, Bb + BK + 4);
        asm volatile("cp.async.commit_group;");
    }

    int cur = 0;   // stage of kt
    for (int kt = 0; kt < nk; kt++) {
        asm volatile("cp.async.wait_group 1;");
        __syncthreads();
        // prefetch kt+2 into stage (cur+2)%3 — safe: all warps are past compute(kt-1)
        int pf = kt + 2;
        if (pf < nk) {
            int ps = cur + 2; if (ps >= 3) ps -= 3;
            const float* ga = Ab + pf * BK;
            const float* gb = Bb + pf * BK;
            float* pa = sA + ps * SSTRIDE;
            float* pb = sB + ps * SSTRIDE;
            cp16(pa, ga); cp16(pa + 4, ga + 4);
            cp16(pb, gb); cp16(pb + 4, gb + 4);
        }
        asm volatile("cp.async.commit_group;");

        const float* as = smem + cur * SSTRIDE;
        const float* bs = as + BM * SROW;
#pragma unroll
        for (int kk = 0; kk < 2; kk++) {
            uint32_t af[4][4], bf[4][2];
#pragma unroll
            for (int mt = 0; mt < 4; mt++) {
                const float* base = &as[(wm * 64 + mt * 16 + g) * SROW + kk * 8 + tg];
                af[mt][0] = __float_as_uint(base[0]);
                af[mt][1] = __float_as_uint(base[8 * SROW]);
                af[mt][2] = __float_as_uint(base[4]);
                af[mt][3] = __float_as_uint(base[8 * SROW + 4]);
            }
#pragma unroll
            for (int nt = 0; nt < 4; nt++) {
                const float* base = &bs[(wn * 32 + nt * 8 + g) * SROW + kk * 8 + tg];
                bf[nt][0] = __float_as_uint(base[0]);
                bf[nt][1] = __float_as_uint(base[4]);
            }
#pragma unroll
            for (int mt = 0; mt < 4; mt++)
#pragma unroll
                for (int nt = 0; nt < 4; nt++)
                    mma_tf32(acc[mt][nt], af[mt], bf[nt]);
        }
        cur++; if (cur == 3) cur = 0;
    }

    // epilogue
#pragma unroll
    for (int mt = 0; mt < 4; mt++) {
#pragma unroll
        for (int nt = 0; nt < 4; nt++) {
            int row0 = bm + wm * 64 + mt * 16 + g;
            int col0 = bn + wn * 32 + nt * 8 + 2 * tg;
#pragma unroll
            for (int h = 0; h < 2; h++) {
                int row = row0 + h * 8;
                float2 r{acc[mt][nt][2 * h], acc[mt][nt][2 * h + 1]};
                size_t off = (size_t)row * Nout + col0;
                if (EPI == 0) {
                    *(float2*)&C[off] = r;
                } else if (EPI == 1) {
                    r.x = 1.f / (1.f + expf(-r.x));
                    r.y = 1.f / (1.f + expf(-r.y));
                    *(float2*)&C[off] = r;
                } else if (EPI == 2) {
                    r.x = fmaxf(r.x, 0.f); r.x = rtf(r.x * r.x);
                    r.y = fmaxf(r.y, 0.f); r.y = rtf(r.y * r.y);
                    *(float2*)&C[off] = r;
                } else if (EPI == 3) {
                    float2 dc = *(float2*)&D[off];
                    dc.x += r.x; dc.y += r.y;
                    *(float2*)&D[off] = dc;
                } else if (EPI == 4) {
                    float2 av = *(const float2*)&aux[off];
                    float2 dc = *(float2*)&D[off];
                    dc.x += av.x * r.x; dc.y += av.y * r.y;
                    *(float2*)&D[off] = dc;
                } else if (EPI == 5) {
                    float2 bv = *(const float2*)&bias[col0];
                    float2 dc = *(float2*)&D[off];
                    dc.x += r.x + bv.x; dc.y += r.y + bv.y;
                    *(float2*)&D[off] = dc;
                }
            }
        }
    }
}

// ---------------- output transpose [N,F] -> [F,N] ----------------
__global__ void out_transpose(float* __restrict__ out) {
    __shared__ float tile[32][33];
    int bn = blockIdx.x * 32;
    int bc = blockIdx.y * 32;
    int tx = threadIdx.x, ty = threadIdx.y;
#pragma unroll
    for (int j = 0; j < 32; j += 8)
        tile[ty + j][tx] = g_d[(size_t)(bn + ty + j) * FD + bc + tx];
    __syncthreads();
#pragma unroll
    for (int j = 0; j < 32; j += 8)
        out[(size_t)(bc + ty + j) * NTOK + bn + tx] = tile[tx][ty + j];
}

// ---------------- host orchestration ----------------
extern "C" void kernel_launch(void* const* d_in, const int* in_sizes, int n_in,
                              void* d_out, int out_size) {
    auto IN = [&](int i) { return (const float*)d_in[i]; };
    const float* x    = IN(0);
    const float* cw1  = IN(1);
    const float* cb1  = IN(2);
    const float* cw2  = IN(3);
    const float* cb2  = IN(4);
    const float* ln0w = IN(5);
    const float* ln0b = IN(6);
    const float* ln1w = IN(7);
    const float* ln1b = IN(8);
    const float* ln2w = IN(9);
    const float* ln2b = IN(10);
    const float* atmk = IN(11);
    const float* atmv = IN(12);
    const float* atmr = IN(13);
    bool sig = (in_sizes[16] > 2048);
    const float *atf, *akw, *avw, *arw, *aow, *ftmk, *ftmr, *fkw, *fvw, *frw;
    if (sig) {
        atf = IN(14);
        akw = IN(16); avw = IN(17); arw = IN(18); aow = IN(19);
        ftmk = IN(20); ftmr = IN(21);
        fkw = IN(22); fvw = IN(23); frw = IN(24);
    } else {
        ftmk = IN(14); ftmr = IN(15);
        atf = IN(16);
        akw = IN(18); avw = IN(19); arw = IN(20); aow = IN(21);
        frw = IN(22); fkw = IN(23); fvw = IN(24);
    }
    const float* sdww = IN(25);
    const float* sdwb = IN(26);
    const float* spww = IN(27);
    const float* spwb = IN(28);
    const float* st   = IN(29);

    float *pd, *pxk, *pxv, *pxr, *pk, *pv, *pr, *prr, *phid, *pdw, *pw, *pwt;
    cudaGetSymbolAddress((void**)&pd,   g_d);
    cudaGetSymbolAddress((void**)&pxk,  g_xk);
    cudaGetSymbolAddress((void**)&pxv,  g_xv);
    cudaGetSymbolAddress((void**)&pxr,  g_xr);
    cudaGetSymbolAddress((void**)&pk,   g_k);
    cudaGetSymbolAddress((void**)&pv,   g_v);
    cudaGetSymbolAddress((void**)&pr,   g_r);
    cudaGetSymbolAddress((void**)&prr,  g_rr);
    cudaGetSymbolAddress((void**)&phid, g_hid);
    cudaGetSymbolAddress((void**)&pdw,  g_dw);
    cudaGetSymbolAddress((void**)&pw,   g_wbuf);
    cudaGetSymbolAddress((void**)&pwt,  g_wtT);

    cudaFuncSetAttribute(gemm_tf32<0>, cudaFuncAttributeMaxDynamicSharedMemorySize, GSMEM);
    cudaFuncSetAttribute(gemm_tf32<1>, cudaFuncAttributeMaxDynamicSharedMemorySize, GSMEM);
    cudaFuncSetAttribute(gemm_tf32<2>, cudaFuncAttributeMaxDynamicSharedMemorySize, GSMEM);
    cudaFuncSetAttribute(gemm_tf32<3>, cudaFuncAttributeMaxDynamicSharedMemorySize, GSMEM);
    cudaFuncSetAttribute(gemm_tf32<4>, cudaFuncAttributeMaxDynamicSharedMemorySize, GSMEM);
    cudaFuncSetAttribute(gemm_tf32<5>, cudaFuncAttributeMaxDynamicSharedMemorySize, GSMEM);

    const dim3 g256(FD / BN, NTOK / BM);     // (2, 200)
    const dim3 g1024(FHID / BN, NTOK / BM);  // (8, 200)
    const dim3 gdw(IMW / 16, IMH / 16, FD / 16);
    const size_t NF = (size_t)NTOK * FD;
    const int SZ256 = NL * FD * FD;

    // ---- launch order arranged so that launch #6 (ncu -s 5 -c 1) is gemm_tf32<0> ----
    stem_kernel<<<NTOK, 256>>>(x, cw1, cb1, cw2, cb2);                              // 1
    cvt_tf32_kernel<<<256, 256>>>(akw, pw + O_AKW, SZ256);                          // 2
    ln_first_mix3_kernel<<<NTOK / 8, 256>>>(ln0w, ln0b, ln1w, ln1b,
                                            atmk, atmv, atmr, st + 1 * NF);         // 3
    wt_all_kernel<<<dim3(49, NL), 256>>>(sdww);                                     // 4
    cvt_tf32_kernel<<<256, 256>>>(avw, pw + O_AVW, SZ256);                          // 5
    gemm_tf32<0><<<g256, 256, GSMEM>>>(pxk, pw + O_AKW, pk, nullptr, nullptr, nullptr, NTOK, FD, FD); // 6 <- profiled
    cvt_tf32_kernel<<<256, 256>>>(arw, pw + O_ARW, SZ256);
    gemm_tf32<0><<<g256, 256, GSMEM>>>(pxv, pw + O_AVW, pv, nullptr, nullptr, nullptr, NTOK, FD, FD);
    cvt_tf32_kernel<<<256, 256>>>(aow, pw + O_AOW, SZ256);
    gemm_tf32<0><<<g256, 256, GSMEM>>>(pxr, pw + O_ARW, pr, nullptr, nullptr, nullptr, NTOK, FD, FD);
    cvt_tf32_kernel<<<1024, 256>>>(fkw, pw + O_FKW, NL * FHID * FD);
    wkv_kernel<<<NTOK, 256>>>(atf, st + 2 * NF, st + 3 * NF, st + 4 * NF);
    cvt_tf32_kernel<<<256, 256>>>(frw, pw + O_FRW, SZ256);
    gemm_tf32<3><<<g256, 256, GSMEM>>>(pxk, pw + O_AOW, nullptr, pd, nullptr, nullptr, NTOK, FD, FD);
    cvt_tf32_kernel<<<1024, 256>>>(fvw, pw + O_FVW, NL * FD * FHID);
    cvt_tf32_kernel<<<256, 256>>>(spww, pw + O_SPW, SZ256);

    for (int i = 0; i < NL; i++) {
        const float* sp0 = st + (size_t)(5 * i + 0) * NF;
        const float* sp1 = st + (size_t)(5 * i + 1) * NF;
        const float* aa  = st + (size_t)(5 * i + 2) * NF;
        const float* bb  = st + (size_t)(5 * i + 3) * NF;
        const float* pp  = st + (size_t)(5 * i + 4) * NF;
        const size_t wo256 = (size_t)i * FD * FD;
        const size_t wo1k  = (size_t)i * FHID * FD;

        if (i > 0) {
            // --- attention (single-step WKV); layer0's attention already issued above ---
            ln_mix3_kernel<<<NTOK / 8, 256>>>(ln1w + i * FD, ln1b + i * FD,
                                              atmk + i * FD, atmv + i * FD, atmr + i * FD, sp1);
            gemm_tf32<0><<<g256, 256, GSMEM>>>(pxk, pw + O_AKW + wo256, pk, nullptr, nullptr, nullptr, NTOK, FD, FD);
            gemm_tf32<0><<<g256, 256, GSMEM>>>(pxv, pw + O_AVW + wo256, pv, nullptr, nullptr, nullptr, NTOK, FD, FD);
            gemm_tf32<0><<<g256, 256, GSMEM>>>(pxr, pw + O_ARW + wo256, pr, nullptr, nullptr, nullptr, NTOK, FD, FD);
            wkv_kernel<<<NTOK, 256>>>(atf + i * FD, aa, bb, pp);
            gemm_tf32<3><<<g256, 256, GSMEM>>>(pxk, pw + O_AOW + wo256, nullptr, pd, nullptr, nullptr, NTOK, FD, FD);
        }

        // --- FFN (squared-relu channel mix) ---
        ln_mix2_kernel<<<NTOK / 8, 256>>>(ln2w + i * FD, ln2b + i * FD,
                                          ftmk + i * FD, ftmr + i * FD, sp0);
        gemm_tf32<2><<<g1024, 256, GSMEM>>>(pxk, pw + O_FKW + wo1k, phid, nullptr, nullptr, nullptr, NTOK, FHID, FD);
        gemm_tf32<1><<<g256, 256, GSMEM>>>(pxr, pw + O_FRW + wo256, prr, nullptr, nullptr, nullptr, NTOK, FD, FD);
        gemm_tf32<4><<<g256, 256, GSMEM>>>(phid, pw + O_FVW + wo1k, nullptr, pd, prr, nullptr, NTOK, FD, FHID);

        // --- spatial residual ---
        dw7t_kernel<<<gdw, 256>>>(sdwb + i * FD, pwt + (size_t)i * 49 * FD);
        gemm_tf32<5><<<g256, 256, GSMEM>>>(pdw, pw + O_SPW + wo256, nullptr, pd, nullptr, spwb + i * FD, NTOK, FD, FD);
    }

    out_transpose<<<dim3(NTOK / 32, FD / 32), dim3(32, 8)>>>((float*)d_out);
}

// round 5
// speedup vs baseline: 3.6628x; 1.4526x over previous
#include <cuda_runtime.h>
#include <cuda_fp16.h>
#include <cstdint>
#include <cstddef>

#define NTOK 25600
#define FD   256
#define FHID 1024
#define IMH  160
#define IMW  160
#define NL   4

// ---------------- scratch (device globals; no allocs allowed) ----------------
__device__ float g_d  [NTOK*FD];                     // residual stream (fp32)
__device__ __align__(16) __half g_xkh[NTOK*FD];
__device__ __align__(16) __half g_xvh[NTOK*FD];
__device__ __align__(16) __half g_xrh[NTOK*FD];
__device__ float g_k  [NTOK*FD];
__device__ float g_v  [NTOK*FD];
__device__ float g_r  [NTOK*FD];
__device__ __align__(16) __half g_gateh[NTOK*FD];    // sigmoid(r)*wkv
__device__ __align__(16) __half g_rrh[NTOK*FD];
__device__ __align__(16) __half g_hidh[NTOK*FHID];
__device__ __align__(16) __half g_dwh[NTOK*FD];
__device__ float g_wtT[NL*49*FD];
__device__ __align__(16) __half g_wbh[3670016];      // fp16 weights

// offsets (elements) into g_wbh
#define O_AKW 0
#define O_AVW 262144
#define O_ARW 524288
#define O_AOW 786432
#define O_FRW 1048576
#define O_SPW 1310720
#define O_FKW 1572864
#define O_FVW 2621440

// ---------------- helpers ----------------
__device__ __forceinline__ float wsum(float v) {
#pragma unroll
    for (int o = 16; o; o >>= 1) v += __shfl_xor_sync(0xffffffffu, v, o);
    return v;
}

__device__ __forceinline__ void ld8(const float* __restrict__ p, float v[8]) {
    float4 a = *(const float4*)p;
    float4 b = *(const float4*)(p + 4);
    v[0]=a.x; v[1]=a.y; v[2]=a.z; v[3]=a.w; v[4]=b.x; v[5]=b.y; v[6]=b.z; v[7]=b.w;
}
__device__ __forceinline__ void st8(float* __restrict__ p, const float v[8]) {
    float4 a{v[0],v[1],v[2],v[3]}, b{v[4],v[5],v[6],v[7]};
    *(float4*)p = a; *(float4*)(p + 4) = b;
}
__device__ __forceinline__ void st8h(__half* __restrict__ p, const float v[8]) {
    union { __half2 h[4]; uint4 u; } t;
    t.h[0] = __floats2half2_rn(v[0], v[1]);
    t.h[1] = __floats2half2_rn(v[2], v[3]);
    t.h[2] = __floats2half2_rn(v[4], v[5]);
    t.h[3] = __floats2half2_rn(v[6], v[7]);
    *(uint4*)p = t.u;
}

// ---------------- weight fp16 pre-conversion ----------------
__global__ void cvt_h_kernel(const float* __restrict__ s, __half* __restrict__ d, int n) {
    int i = (blockIdx.x * 256 + threadIdx.x) * 8;
    if (i < n) {
        float v[8]; ld8(s + i, v);
        st8h(d + i, v);
    }
}

// LayerNorm over 256 features: one warp per token, 8 features per lane (input from g_d).
__device__ __forceinline__ void ln_compute(int n, int lane,
                                           const float* __restrict__ lw,
                                           const float* __restrict__ lb,
                                           float xs[8]) {
    const float* row = g_d + (size_t)n * FD + lane * 8;
    float v[8]; ld8(row, v);
    float s = v[0]+v[1]+v[2]+v[3]+v[4]+v[5]+v[6]+v[7];
    float mu = wsum(s) * (1.f / 256.f);
    float q = 0.f;
#pragma unroll
    for (int t = 0; t < 8; t++) { float dd = v[t] - mu; q += dd * dd; }
    float rs = rsqrtf(wsum(q) * (1.f / 256.f) + 1e-5f);
    float wv[8], bv[8];
    ld8(lw + lane*8, wv); ld8(lb + lane*8, bv);
#pragma unroll
    for (int t = 0; t < 8; t++) xs[t] = (v[t] - mu) * rs * wv[t] + bv[t];
}

__device__ __forceinline__ void ln_regs(const float in[8], int lane,
                                        const float* __restrict__ lw,
                                        const float* __restrict__ lb,
                                        float xs[8]) {
    float s = in[0]+in[1]+in[2]+in[3]+in[4]+in[5]+in[6]+in[7];
    float mu = wsum(s) * (1.f / 256.f);
    float q = 0.f;
#pragma unroll
    for (int t = 0; t < 8; t++) { float dd = in[t] - mu; q += dd * dd; }
    float rs = rsqrtf(wsum(q) * (1.f / 256.f) + 1e-5f);
    float wv[8], bv[8];
    ld8(lw + lane*8, wv); ld8(lb + lane*8, bv);
#pragma unroll
    for (int t = 0; t < 8; t++) xs[t] = (in[t] - mu) * rs * wv[t] + bv[t];
}

// ---------------- stem ----------------
__global__ void stem_kernel(const float* __restrict__ x,
                            const float* __restrict__ w1, const float* __restrict__ b1,
                            const float* __restrict__ w2, const float* __restrict__ b2) {
    int n = blockIdx.x;
    int h = n / IMW, w = n % IMW;
    int c = threadIdx.x;
    __shared__ float sx[49];
    __shared__ float sm[49];
    if (threadIdx.x < 49) {
        int u = threadIdx.x / 7, vv = threadIdx.x % 7;
        int hh = h + u - 3, ww = w + vv - 3;
        bool in = (hh >= 0 && hh < IMH && ww >= 0 && ww < IMW);
        sx[threadIdx.x] = in ? x[hh * IMW + ww] : 0.f;
        sm[threadIdx.x] = in ? 1.f : 0.f;
    }
    __syncthreads();
    float a = w1[c], bb = b1[c];
    float acc = b2[c];
#pragma unroll
    for (int t = 0; t < 49; t++)
        acc += (sx[t] * a + bb * sm[t]) * w2[c * 49 + t];
    float s = 1.f / (1.f + expf(-4.f * acc));
    g_d[(size_t)n * FD + c] = s * acc;
}

// ---------------- LN + mix kernels ----------------
__device__ __forceinline__ void mix3_store(const float xs[8], int lane, size_t base,
                                           const float* __restrict__ tmk,
                                           const float* __restrict__ tmv,
                                           const float* __restrict__ tmr,
                                           const float* __restrict__ sp) {
    int j = lane * 8;
    float spv[8], mk[8], mv[8], mr[8];
    ld8(sp + base, spv); ld8(tmk + j, mk); ld8(tmv + j, mv); ld8(tmr + j, mr);
    float ok[8], ov[8], orr[8];
#pragma unroll
    for (int t = 0; t < 8; t++) {
        ok[t]  = xs[t] * mk[t] + spv[t] * (1.f - mk[t]);
        ov[t]  = xs[t] * mv[t] + spv[t] * (1.f - mv[t]);
        orr[t] = xs[t] * mr[t] + spv[t] * (1.f - mr[t]);
    }
    st8h(g_xkh + base, ok); st8h(g_xvh + base, ov); st8h(g_xrh + base, orr);
}

__global__ void ln_mix3_kernel(const float* __restrict__ lw, const float* __restrict__ lb,
                               const float* __restrict__ tmk, const float* __restrict__ tmv,
                               const float* __restrict__ tmr, const float* __restrict__ sp) {
    int n = blockIdx.x * 8 + (threadIdx.x >> 5);
    int lane = threadIdx.x & 31;
    float xs[8];
    ln_compute(n, lane, lw, lb, xs);
    mix3_store(xs, lane, (size_t)n * FD + lane * 8, tmk, tmv, tmr, sp);
}

__global__ void ln_first_mix3_kernel(const float* __restrict__ l0w, const float* __restrict__ l0b,
                                     const float* __restrict__ lw, const float* __restrict__ lb,
                                     const float* __restrict__ tmk, const float* __restrict__ tmv,
                                     const float* __restrict__ tmr, const float* __restrict__ sp) {
    int n = blockIdx.x * 8 + (threadIdx.x >> 5);
    int lane = threadIdx.x & 31;
    float xs0[8];
    ln_compute(n, lane, l0w, l0b, xs0);
    size_t base = (size_t)n * FD + lane * 8;
    st8(g_d + base, xs0);
    float xs[8];
    ln_regs(xs0, lane, lw, lb, xs);
    mix3_store(xs, lane, base, tmk, tmv, tmr, sp);
}

__global__ void ln_mix2_kernel(const float* __restrict__ lw, const float* __restrict__ lb,
                               const float* __restrict__ tmk, const float* __restrict__ tmr,
                               const float* __restrict__ sp) {
    int n = blockIdx.x * 8 + (threadIdx.x >> 5);
    int lane = threadIdx.x & 31;
    float xs[8];
    ln_compute(n, lane, lw, lb, xs);
    size_t base = (size_t)n * FD + lane * 8;
    int j = lane * 8;
    float spv[8], mk[8], mr[8];
    ld8(sp + base, spv); ld8(tmk + j, mk); ld8(tmr + j, mr);
    float ok[8], orr[8];
#pragma unroll
    for (int t = 0; t < 8; t++) {
        ok[t]  = xs[t] * mk[t] + spv[t] * (1.f - mk[t]);
        orr[t] = xs[t] * mr[t] + spv[t] * (1.f - mr[t]);
    }
    st8h(g_xkh + base, ok); st8h(g_xrh + base, orr);
}

// ---------------- WKV single step + sigmoid gate (4 elems/thread) ----------------
__global__ void wkv_kernel(const float* __restrict__ tf, const float* __restrict__ aa,
                           const float* __restrict__ bb, const float* __restrict__ pp) {
    size_t idx = ((size_t)blockIdx.x * 256 + threadIdx.x) * 4;
    int c = (int)(idx & (FD - 1));
    float4 k4 = *(const float4*)&g_k[idx];
    float4 v4 = *(const float4*)&g_v[idx];
    float4 r4 = *(const float4*)&g_r[idx];
    float4 tf4 = *(const float4*)&tf[c];
    float4 aa4 = *(const float4*)&aa[idx];
    float4 bb4 = *(const float4*)&bb[idx];
    float4 pp4 = *(const float4*)&pp[idx];
    float o[4];
    float kk[4] = {k4.x, k4.y, k4.z, k4.w};
    float vv[4] = {v4.x, v4.y, v4.z, v4.w};
    float rr[4] = {r4.x, r4.y, r4.z, r4.w};
    float tfv[4] = {tf4.x, tf4.y, tf4.z, tf4.w};
    float aav[4] = {aa4.x, aa4.y, aa4.z, aa4.w};
    float bbv[4] = {bb4.x, bb4.y, bb4.z, bb4.w};
    float ppv[4] = {pp4.x, pp4.y, pp4.z, pp4.w};
#pragma unroll
    for (int t = 0; t < 4; t++) {
        float ww = tfv[t] + kk[t];
        float p = fmaxf(ppv[t], ww);
        float e1 = expf(ppv[t] - p), e2 = expf(ww - p);
        float wkv = (e1 * aav[t] + e2 * vv[t]) / (e1 * bbv[t] + e2);
        float sig = 1.f / (1.f + expf(-rr[t]));
        o[t] = sig * wkv;
    }
    union { __half2 h[2]; uint2 u; } out;
    out.h[0] = __floats2half2_rn(o[0], o[1]);
    out.h[1] = __floats2half2_rn(o[2], o[3]);
    *(uint2*)&g_gateh[idx] = out.u;
}

// ---------------- depthwise 7x7 ----------------
__global__ void wt_all_kernel(const float* __restrict__ wt) {
    int l = blockIdx.y, tap = blockIdx.x, c = threadIdx.x;
    g_wtT[(l * 49 + tap) * FD + c] = wt[(l * FD + c) * 49 + tap];
}

__global__ __launch_bounds__(256)
void dw7t_kernel(const float* __restrict__ bias, const float* __restrict__ wtT) {
    __shared__ float tile[22 * 22 * 16];
    __shared__ float ws[49 * 16];
    __shared__ float bs[16];
    const int w0 = blockIdx.x * 16, h0 = blockIdx.y * 16, cb = blockIdx.z * 16;
    const int tid = threadIdx.x;

    if (tid < 196) {
        int t = tid >> 2, c4 = (tid & 3) * 4;
        *(float4*)&ws[t * 16 + c4] = *(const float4*)&wtT[t * FD + cb + c4];
    }
    if (tid < 16) bs[tid] = bias[cb + tid];

    for (int idx = tid; idx < 22 * 22 * 4; idx += 256) {
        int pos = idx >> 2, c4 = (idx & 3) * 4;
        int ih = pos / 22, iw = pos % 22;
        int gh = h0 + ih - 3, gw = w0 + iw - 3;
        float4 v{0.f, 0.f, 0.f, 0.f};
        if (gh >= 0 && gh < IMH && gw >= 0 && gw < IMW)
            v = *(const float4*)&g_d[((size_t)gh * IMW + gw) * FD + cb + c4];
        *(float4*)&tile[pos * 16 + c4] = v;
    }
    __syncthreads();

    const int c4id = tid & 3;
    const int sbase = tid >> 2;
    float acc[4][4];
    float4 bv = *(const float4*)&bs[c4id * 4];
#pragma unroll
    for (int j = 0; j < 4; j++) { acc[j][0] = bv.x; acc[j][1] = bv.y; acc[j][2] = bv.z; acc[j][3] = bv.w; }

#pragma unroll
    for (int u = 0; u < 7; u++) {
#pragma unroll
        for (int v7 = 0; v7 < 7; v7++) {
            float4 wv = *(const float4*)&ws[(u * 7 + v7) * 16 + c4id * 4];
#pragma unroll
            for (int j = 0; j < 4; j++) {
                int s = sbase + 64 * j;
                int sy = s >> 4, sx = s & 15;
                float4 tv = *(const float4*)&tile[((sy + u) * 22 + (sx + v7)) * 16 + c4id * 4];
                acc[j][0] += tv.x * wv.x; acc[j][1] += tv.y * wv.y;
                acc[j][2] += tv.z * wv.z; acc[j][3] += tv.w * wv.w;
            }
        }
    }
#pragma unroll
    for (int j = 0; j < 4; j++) {
        int s = sbase + 64 * j;
        int sy = s >> 4, sx = s & 15;
        union { __half2 h[2]; uint2 u; } t;
        t.h[0] = __floats2half2_rn(acc[j][0], acc[j][1]);
        t.h[1] = __floats2half2_rn(acc[j][2], acc[j][3]);
        *(uint2*)&g_dwh[((size_t)(h0 + sy) * IMW + (w0 + sx)) * FD + cb + c4id * 4] = t.u;
    }
}

// ---------------- FP16 tensor-core NT GEMM, 3-stage cp.async ----------------
// C[M,Nout] = A[M,K] @ W[Nout,K]^T via mma.m16n8k16.f16, fp32 accum.
#define BM 128
#define BN 128
#define BKH 32                         // k per tile (halfs)
#define SROWH 40                       // padded row stride (halfs)
#define SROWW 20                       // same in 32-bit words
#define SSTRIDEH ((BM + BN) * SROWH)   // halfs per stage (10240)
#define GSMEM (3 * SSTRIDEH * 2)       // bytes (61440)

__device__ __forceinline__ void mma_f16(float c[4], const uint32_t a[4], const uint32_t b[2]) {
    asm volatile(
        "mma.sync.aligned.m16n8k16.row.col.f32.f16.f16.f32 "
        "{%0,%1,%2,%3}, {%4,%5,%6,%7}, {%8,%9}, {%0,%1,%2,%3};"
        : "+f"(c[0]), "+f"(c[1]), "+f"(c[2]), "+f"(c[3])
        : "r"(a[0]), "r"(a[1]), "r"(a[2]), "r"(a[3]), "r"(b[0]), "r"(b[1]));
}

__device__ __forceinline__ void cp16(__half* smem, const __half* g) {
    uint32_t s = (uint32_t)__cvta_generic_to_shared(smem);
    asm volatile("cp.async.cg.shared.global [%0], [%1], 16;" :: "r"(s), "l"(g));
}

// EPI 0: C(float)=acc | 1: Ch=sigmoid | 2: Ch=relu^2 | 3: D+=acc | 4: D+=aux(half)*acc | 5: D+=acc+bias
template <int EPI>
__device__ __forceinline__ void gemm_body(
    const __half* __restrict__ A, const __half* __restrict__ Wm,
    float* __restrict__ C, __half* __restrict__ Ch, float* __restrict__ D,
    const __half* __restrict__ aux, const float* __restrict__ bias,
    int M, int Nout, int K, __half* smemh) {

    const int tid  = threadIdx.x;
    const int bm   = blockIdx.y * BM;
    const int bn   = blockIdx.x * BN;
    const int wid  = tid >> 5;
    const int lane = tid & 31;
    const int wm   = wid & 1;
    const int wn   = wid >> 1;
    const int g    = lane >> 2;
    const int tg   = lane & 3;

    const int lrow = tid >> 1;            // 0..127
    const int lkc  = (tid & 1) * 16;      // 0 or 16 halfs

    const __half* Ab = A  + (size_t)(bm + lrow) * K + lkc;
    const __half* Bb = Wm + (size_t)(bn + lrow) * K + lkc;
    __half* const sA = smemh + lrow * SROWH + lkc;
    __half* const sB = smemh + BM * SROWH + lrow * SROWH + lkc;

    float acc[4][4][4];
#pragma unroll
    for (int i = 0; i < 4; i++)
#pragma unroll
        for (int j = 0; j < 4; j++)
#pragma unroll
            for (int t = 0; t < 4; t++) acc[i][j][t] = 0.f;

    const int nk = K / BKH;

    cp16(sA, Ab); cp16(sA + 8, Ab + 8);
    cp16(sB, Bb); cp16(sB + 8, Bb + 8);
    asm volatile("cp.async.commit_group;");
    cp16(sA + SSTRIDEH, Ab + BKH); cp16(sA + SSTRIDEH + 8, Ab + BKH + 8);
    cp16(sB + SSTRIDEH, Bb + BKH); cp16(sB + SSTRIDEH + 8, Bb + BKH + 8);
    asm volatile("cp.async.commit_group;");

    int cur = 0;
    for (int kt = 0; kt < nk; kt++) {
        asm volatile("cp.async.wait_group 1;");
        __syncthreads();
        int pf = kt + 2;
        if (pf < nk) {
            int ps = cur + 2; if (ps >= 3) ps -= 3;
            const __half* ga = Ab + pf * BKH;
            const __half* gb = Bb + pf * BKH;
            __half* pa = sA + ps * SSTRIDEH;
            __half* pb = sB + ps * SSTRIDEH;
            cp16(pa, ga); cp16(pa + 8, ga + 8);
            cp16(pb, gb); cp16(pb + 8, gb + 8);
        }
        asm volatile("cp.async.commit_group;");

        const uint32_t* as = (const uint32_t*)(smemh + cur * SSTRIDEH);
        const uint32_t* bs = as + BM * SROWW;
#pragma unroll
        for (int kk = 0; kk < 2; kk++) {
            uint32_t af[4][4], bf[4][2];
#pragma unroll
            for (int mt = 0; mt < 4; mt++) {
                const uint32_t* base = &as[(wm * 64 + mt * 16 + g) * SROWW + kk * 8 + tg];
                af[mt][0] = base[0];
                af[mt][1] = base[8 * SROWW];
                af[mt][2] = base[4];
                af[mt][3] = base[8 * SROWW + 4];
            }
#pragma unroll
            for (int nt = 0; nt < 4; nt++) {
                const uint32_t* base = &bs[(wn * 32 + nt * 8 + g) * SROWW + kk * 8 + tg];
                bf[nt][0] = base[0];
                bf[nt][1] = base[4];
            }
#pragma unroll
            for (int mt = 0; mt < 4; mt++)
#pragma unroll
                for (int nt = 0; nt < 4; nt++)
                    mma_f16(acc[mt][nt], af[mt], bf[nt]);
        }
        cur++; if (cur == 3) cur = 0;
    }

    // epilogue
#pragma unroll
    for (int mt = 0; mt < 4; mt++) {
#pragma unroll
        for (int nt = 0; nt < 4; nt++) {
            int row0 = bm + wm * 64 + mt * 16 + g;
            int col0 = bn + wn * 32 + nt * 8 + 2 * tg;
#pragma unroll
            for (int h = 0; h < 2; h++) {
                int row = row0 + h * 8;
                float rx = acc[mt][nt][2 * h], ry = acc[mt][nt][2 * h + 1];
                size_t off = (size_t)row * Nout + col0;
                if (EPI == 0) {
                    *(float2*)&C[off] = float2{rx, ry};
                } else if (EPI == 1) {
                    rx = 1.f / (1.f + expf(-rx));
                    ry = 1.f / (1.f + expf(-ry));
                    *(__half2*)&Ch[off] = __floats2half2_rn(rx, ry);
                } else if (EPI == 2) {
                    rx = fmaxf(rx, 0.f); rx *= rx;
                    ry = fmaxf(ry, 0.f); ry *= ry;
                    *(__half2*)&Ch[off] = __floats2half2_rn(rx, ry);
                } else if (EPI == 3) {
                    float2 dc = *(float2*)&D[off];
                    dc.x += rx; dc.y += ry;
                    *(float2*)&D[off] = dc;
                } else if (EPI == 4) {
                    __half2 av = *(const __half2*)&aux[off];
                    float2 afv = __half22float2(av);
                    float2 dc = *(float2*)&D[off];
                    dc.x += afv.x * rx; dc.y += afv.y * ry;
                    *(float2*)&D[off] = dc;
                } else if (EPI == 5) {
                    float2 bv = *(const float2*)&bias[col0];
                    float2 dc = *(float2*)&D[off];
                    dc.x += rx + bv.x; dc.y += ry + bv.y;
                    *(float2*)&D[off] = dc;
                }
            }
        }
    }
}

template <int EPI>
__global__ __launch_bounds__(256, 2)
void gemm_h(const __half* A, const __half* W, float* C, __half* Ch, float* D,
            const __half* aux, const float* bias, int M, int Nout, int K) {
    extern __shared__ __half sh[];
    gemm_body<EPI>(A, W, C, Ch, D, aux, bias, M, Nout, K, sh);
}

struct Ptr3 {
    const __half* A[3];
    const __half* W[3];
    float* C[3];
};

__global__ __launch_bounds__(256, 2)
void gemm_kvr(Ptr3 p, int M, int Nout, int K) {
    extern __shared__ __half sh[];
    int z = blockIdx.z;
    gemm_body<0>(p.A[z], p.W[z], p.C[z], nullptr, nullptr, nullptr, nullptr, M, Nout, K, sh);
}

// ---------------- output transpose [N,F] -> [F,N] ----------------
__global__ void out_transpose(float* __restrict__ out) {
    __shared__ float tile[32][33];
    int bn = blockIdx.x * 32;
    int bc = blockIdx.y * 32;
    int tx = threadIdx.x, ty = threadIdx.y;
#pragma unroll
    for (int j = 0; j < 32; j += 8)
        tile[ty + j][tx] = g_d[(size_t)(bn + ty + j) * FD + bc + tx];
    __syncthreads();
#pragma unroll
    for (int j = 0; j < 32; j += 8)
        out[(size_t)(bc + ty + j) * NTOK + bn + tx] = tile[tx][ty + j];
}

// ---------------- host orchestration ----------------
extern "C" void kernel_launch(void* const* d_in, const int* in_sizes, int n_in,
                              void* d_out, int out_size) {
    auto IN = [&](int i) { return (const float*)d_in[i]; };
    const float* x    = IN(0);
    const float* cw1  = IN(1);
    const float* cb1  = IN(2);
    const float* cw2  = IN(3);
    const float* cb2  = IN(4);
    const float* ln0w = IN(5);
    const float* ln0b = IN(6);
    const float* ln1w = IN(7);
    const float* ln1b = IN(8);
    const float* ln2w = IN(9);
    const float* ln2b = IN(10);
    const float* atmk = IN(11);
    const float* atmv = IN(12);
    const float* atmr = IN(13);
    bool sig = (in_sizes[16] > 2048);
    const float *atf, *akw, *avw, *arw, *aow, *ftmk, *ftmr, *fkw, *fvw, *frw;
    if (sig) {
        atf = IN(14);
        akw = IN(16); avw = IN(17); arw = IN(18); aow = IN(19);
        ftmk = IN(20); ftmr = IN(21);
        fkw = IN(22); fvw = IN(23); frw = IN(24);
    } else {
        ftmk = IN(14); ftmr = IN(15);
        atf = IN(16);
        akw = IN(18); avw = IN(19); arw = IN(20); aow = IN(21);
        frw = IN(22); fkw = IN(23); fvw = IN(24);
    }
    const float* sdww = IN(25);
    const float* sdwb = IN(26);
    const float* spww = IN(27);
    const float* spwb = IN(28);
    const float* st   = IN(29);

    float *pd, *pk, *pv, *pr, *pwt;
    __half *pxk, *pxv, *pxr, *pgate, *prr, *phid, *pdw, *pw;
    cudaGetSymbolAddress((void**)&pd,    g_d);
    cudaGetSymbolAddress((void**)&pxk,   g_xkh);
    cudaGetSymbolAddress((void**)&pxv,   g_xvh);
    cudaGetSymbolAddress((void**)&pxr,   g_xrh);
    cudaGetSymbolAddress((void**)&pk,    g_k);
    cudaGetSymbolAddress((void**)&pv,    g_v);
    cudaGetSymbolAddress((void**)&pr,    g_r);
    cudaGetSymbolAddress((void**)&pgate, g_gateh);
    cudaGetSymbolAddress((void**)&prr,   g_rrh);
    cudaGetSymbolAddress((void**)&phid,  g_hidh);
    cudaGetSymbolAddress((void**)&pdw,   g_dwh);
    cudaGetSymbolAddress((void**)&pw,    g_wbh);
    cudaGetSymbolAddress((void**)&pwt,   g_wtT);

    cudaFuncSetAttribute(gemm_h<1>, cudaFuncAttributeMaxDynamicSharedMemorySize, GSMEM);
    cudaFuncSetAttribute(gemm_h<2>, cudaFuncAttributeMaxDynamicSharedMemorySize, GSMEM);
    cudaFuncSetAttribute(gemm_h<3>, cudaFuncAttributeMaxDynamicSharedMemorySize, GSMEM);
    cudaFuncSetAttribute(gemm_h<4>, cudaFuncAttributeMaxDynamicSharedMemorySize, GSMEM);
    cudaFuncSetAttribute(gemm_h<5>, cudaFuncAttributeMaxDynamicSharedMemorySize, GSMEM);
    cudaFuncSetAttribute(gemm_kvr,  cudaFuncAttributeMaxDynamicSharedMemorySize, GSMEM);

    const dim3 g256(FD / BN, NTOK / BM);       // (2, 200)
    const dim3 gkvr(FD / BN, NTOK / BM, 3);    // (2, 200, 3)
    const dim3 g1024(FHID / BN, NTOK / BM);    // (8, 200)
    const dim3 gdw(IMW / 16, IMH / 16, FD / 16);
    const size_t NF = (size_t)NTOK * FD;
    const int SZ256 = NL * FD * FD;
    const int SZ1K  = NL * FHID * FD;

    // weight pre-conversion to fp16
    cvt_h_kernel<<<SZ256 / 2048, 256>>>(akw, pw + O_AKW, SZ256);
    cvt_h_kernel<<<SZ256 / 2048, 256>>>(avw, pw + O_AVW, SZ256);
    cvt_h_kernel<<<SZ256 / 2048, 256>>>(arw, pw + O_ARW, SZ256);
    cvt_h_kernel<<<SZ256 / 2048, 256>>>(aow, pw + O_AOW, SZ256);
    cvt_h_kernel<<<SZ256 / 2048, 256>>>(frw, pw + O_FRW, SZ256);
    cvt_h_kernel<<<SZ256 / 2048, 256>>>(spww, pw + O_SPW, SZ256);
    cvt_h_kernel<<<SZ1K / 2048, 256>>>(fkw, pw + O_FKW, SZ1K);
    cvt_h_kernel<<<SZ1K / 2048, 256>>>(fvw, pw + O_FVW, SZ1K);

    stem_kernel<<<NTOK, 256>>>(x, cw1, cb1, cw2, cb2);
    wt_all_kernel<<<dim3(49, NL), 256>>>(sdww);

    for (int i = 0; i < NL; i++) {
        const float* sp0 = st + (size_t)(5 * i + 0) * NF;
        const float* sp1 = st + (size_t)(5 * i + 1) * NF;
        const float* aa  = st + (size_t)(5 * i + 2) * NF;
        const float* bb  = st + (size_t)(5 * i + 3) * NF;
        const float* pp  = st + (size_t)(5 * i + 4) * NF;
        const size_t wo256 = (size_t)i * FD * FD;
        const size_t wo1k  = (size_t)i * FHID * FD;

        // --- attention (single-step WKV) ---
        if (i == 0)
            ln_first_mix3_kernel<<<NTOK / 8, 256>>>(ln0w, ln0b, ln1w, ln1b,
                                                    atmk, atmv, atmr, sp1);
        else
            ln_mix3_kernel<<<NTOK / 8, 256>>>(ln1w + i * FD, ln1b + i * FD,
                                              atmk + i * FD, atmv + i * FD, atmr + i * FD, sp1);
        Ptr3 p3;
        p3.A[0] = pxk; p3.A[1] = pxv; p3.A[2] = pxr;
        p3.W[0] = pw + O_AKW + wo256; p3.W[1] = pw + O_AVW + wo256; p3.W[2] = pw + O_ARW + wo256;
        p3.C[0] = pk; p3.C[1] = pv; p3.C[2] = pr;
        gemm_kvr<<<gkvr, 256, GSMEM>>>(p3, NTOK, FD, FD);
        wkv_kernel<<<NTOK * FD / 1024, 256>>>(atf + i * FD, aa, bb, pp);
        gemm_h<3><<<g256, 256, GSMEM>>>(pgate, pw + O_AOW + wo256, nullptr, nullptr, pd, nullptr, nullptr, NTOK, FD, FD);

        // --- FFN (squared-relu channel mix) ---
        ln_mix2_kernel<<<NTOK / 8, 256>>>(ln2w + i * FD, ln2b + i * FD,
                                          ftmk + i * FD, ftmr + i * FD, sp0);
        gemm_h<2><<<g1024, 256, GSMEM>>>(pxk, pw + O_FKW + wo1k, nullptr, phid, nullptr, nullptr, nullptr, NTOK, FHID, FD);
        gemm_h<1><<<g256, 256, GSMEM>>>(pxr, pw + O_FRW + wo256, nullptr, prr, nullptr, nullptr, nullptr, NTOK, FD, FD);
        gemm_h<4><<<g256, 256, GSMEM>>>(phid, pw + O_FVW + wo1k, nullptr, nullptr, pd, prr, nullptr, NTOK, FD, FHID);

        // --- spatial residual ---
        dw7t_kernel<<<gdw, 256>>>(sdwb + i * FD, pwt + (size_t)i * 49 * FD);
        gemm_h<5><<<g256, 256, GSMEM>>>(pdw, pw + O_SPW + wo256, nullptr, nullptr, pd, nullptr, spwb + i * FD, NTOK, FD, FD);
    }

    out_transpose<<<dim3(NTOK / 32, FD / 32), dim3(32, 8)>>>((float*)d_out);
}

// round 6
// speedup vs baseline: 3.9005x; 1.0649x over previous
#include <cuda_runtime.h>
#include <cuda_fp16.h>
#include <cstdint>
#include <cstddef>

#define NTOK 25600
#define FD   256
#define FHID 1024
#define IMH  160
#define IMW  160
#define NL   4

// ---------------- scratch (device globals; no allocs allowed) ----------------
__device__ float g_d  [NTOK*FD];                     // residual stream (fp32)
__device__ __align__(16) __half g_xkh[NTOK*FD];
__device__ __align__(16) __half g_xvh[NTOK*FD];
__device__ __align__(16) __half g_xrh[NTOK*FD];
__device__ float g_k  [NTOK*FD];
__device__ float g_v  [NTOK*FD];
__device__ float g_r  [NTOK*FD];
__device__ __align__(16) __half g_gateh[NTOK*FD];    // sigmoid(r)*wkv
__device__ __align__(16) __half g_rrh[NTOK*FD];
__device__ __align__(16) __half g_hidh[NTOK*FHID];
__device__ __align__(16) __half g_dwh[NTOK*FD];
__device__ float g_wtT[NL*49*FD];
__device__ __align__(16) __half g_wbh[3670016];      // fp16 weights

// offsets (elements) into g_wbh
#define O_AKW 0
#define O_AVW 262144
#define O_ARW 524288
#define O_AOW 786432
#define O_FRW 1048576
#define O_SPW 1310720
#define O_FKW 1572864
#define O_FVW 2621440

// ---------------- helpers ----------------
__device__ __forceinline__ float wsum(float v) {
#pragma unroll
    for (int o = 16; o; o >>= 1) v += __shfl_xor_sync(0xffffffffu, v, o);
    return v;
}

__device__ __forceinline__ void ld8(const float* __restrict__ p, float v[8]) {
    float4 a = *(const float4*)p;
    float4 b = *(const float4*)(p + 4);
    v[0]=a.x; v[1]=a.y; v[2]=a.z; v[3]=a.w; v[4]=b.x; v[5]=b.y; v[6]=b.z; v[7]=b.w;
}
__device__ __forceinline__ void st8(float* __restrict__ p, const float v[8]) {
    float4 a{v[0],v[1],v[2],v[3]}, b{v[4],v[5],v[6],v[7]};
    *(float4*)p = a; *(float4*)(p + 4) = b;
}
__device__ __forceinline__ void st8h(__half* __restrict__ p, const float v[8]) {
    union { __half2 h[4]; uint4 u; } t;
    t.h[0] = __floats2half2_rn(v[0], v[1]);
    t.h[1] = __floats2half2_rn(v[2], v[3]);
    t.h[2] = __floats2half2_rn(v[4], v[5]);
    t.h[3] = __floats2half2_rn(v[6], v[7]);
    *(uint4*)p = t.u;
}

// ---------------- batched weight fp16 pre-conversion (single launch) ----------------
struct Src8 { const float* p[8]; };

__global__ void cvt_all_kernel(Src8 s) {
    int bx = blockIdx.x;
    int t, boff; size_t dstoff;
    if (bx < 768)        { t = bx >> 7; boff = bx & 127;  dstoff = (size_t)t * 262144; }
    else if (bx < 1280)  { t = 6;       boff = bx - 768;  dstoff = O_FKW; }
    else                 { t = 7;       boff = bx - 1280; dstoff = O_FVW; }
    int i = (boff * 256 + threadIdx.x) * 8;
    float v[8]; ld8(s.p[t] + i, v);
    st8h(g_wbh + dstoff + i, v);
}

// LayerNorm over 256 features: one warp per token, 8 features per lane (input from g_d).
__device__ __forceinline__ void ln_compute(int n, int lane,
                                           const float* __restrict__ lw,
                                           const float* __restrict__ lb,
                                           float xs[8]) {
    const float* row = g_d + (size_t)n * FD + lane * 8;
    float v[8]; ld8(row, v);
    float s = v[0]+v[1]+v[2]+v[3]+v[4]+v[5]+v[6]+v[7];
    float mu = wsum(s) * (1.f / 256.f);
    float q = 0.f;
#pragma unroll
    for (int t = 0; t < 8; t++) { float dd = v[t] - mu; q += dd * dd; }
    float rs = rsqrtf(wsum(q) * (1.f / 256.f) + 1e-5f);
    float wv[8], bv[8];
    ld8(lw + lane*8, wv); ld8(lb + lane*8, bv);
#pragma unroll
    for (int t = 0; t < 8; t++) xs[t] = (v[t] - mu) * rs * wv[t] + bv[t];
}

__device__ __forceinline__ void ln_regs(const float in[8], int lane,
                                        const float* __restrict__ lw,
                                        const float* __restrict__ lb,
                                        float xs[8]) {
    float s = in[0]+in[1]+in[2]+in[3]+in[4]+in[5]+in[6]+in[7];
    float mu = wsum(s) * (1.f / 256.f);
    float q = 0.f;
#pragma unroll
    for (int t = 0; t < 8; t++) { float dd = in[t] - mu; q += dd * dd; }
    float rs = rsqrtf(wsum(q) * (1.f / 256.f) + 1e-5f);
    float wv[8], bv[8];
    ld8(lw + lane*8, wv); ld8(lb + lane*8, bv);
#pragma unroll
    for (int t = 0; t < 8; t++) xs[t] = (in[t] - mu) * rs * wv[t] + bv[t];
}

// ---------------- stem ----------------
__global__ void stem_kernel(const float* __restrict__ x,
                            const float* __restrict__ w1, const float* __restrict__ b1,
                            const float* __restrict__ w2, const float* __restrict__ b2) {
    int n = blockIdx.x;
    int h = n / IMW, w = n % IMW;
    int c = threadIdx.x;
    __shared__ float sx[49];
    __shared__ float sm[49];
    if (threadIdx.x < 49) {
        int u = threadIdx.x / 7, vv = threadIdx.x % 7;
        int hh = h + u - 3, ww = w + vv - 3;
        bool in = (hh >= 0 && hh < IMH && ww >= 0 && ww < IMW);
        sx[threadIdx.x] = in ? x[hh * IMW + ww] : 0.f;
        sm[threadIdx.x] = in ? 1.f : 0.f;
    }
    __syncthreads();
    float a = w1[c], bb = b1[c];
    float acc = b2[c];
#pragma unroll
    for (int t = 0; t < 49; t++)
        acc += (sx[t] * a + bb * sm[t]) * w2[c * 49 + t];
    float s = 1.f / (1.f + expf(-4.f * acc));
    g_d[(size_t)n * FD + c] = s * acc;
}

// ---------------- LN + mix kernels ----------------
__device__ __forceinline__ void mix3_store(const float xs[8], int lane, size_t base,
                                           const float* __restrict__ tmk,
                                           const float* __restrict__ tmv,
                                           const float* __restrict__ tmr,
                                           const float* __restrict__ sp) {
    int j = lane * 8;
    float spv[8], mk[8], mv[8], mr[8];
    ld8(sp + base, spv); ld8(tmk + j, mk); ld8(tmv + j, mv); ld8(tmr + j, mr);
    float ok[8], ov[8], orr[8];
#pragma unroll
    for (int t = 0; t < 8; t++) {
        ok[t]  = xs[t] * mk[t] + spv[t] * (1.f - mk[t]);
        ov[t]  = xs[t] * mv[t] + spv[t] * (1.f - mv[t]);
        orr[t] = xs[t] * mr[t] + spv[t] * (1.f - mr[t]);
    }
    st8h(g_xkh + base, ok); st8h(g_xvh + base, ov); st8h(g_xrh + base, orr);
}

__global__ void ln_mix3_kernel(const float* __restrict__ lw, const float* __restrict__ lb,
                               const float* __restrict__ tmk, const float* __restrict__ tmv,
                               const float* __restrict__ tmr, const float* __restrict__ sp) {
    int n = blockIdx.x * 8 + (threadIdx.x >> 5);
    int lane = threadIdx.x & 31;
    float xs[8];
    ln_compute(n, lane, lw, lb, xs);
    mix3_store(xs, lane, (size_t)n * FD + lane * 8, tmk, tmv, tmr, sp);
}

__global__ void ln_first_mix3_kernel(const float* __restrict__ l0w, const float* __restrict__ l0b,
                                     const float* __restrict__ lw, const float* __restrict__ lb,
                                     const float* __restrict__ tmk, const float* __restrict__ tmv,
                                     const float* __restrict__ tmr, const float* __restrict__ sp) {
    int n = blockIdx.x * 8 + (threadIdx.x >> 5);
    int lane = threadIdx.x & 31;
    float xs0[8];
    ln_compute(n, lane, l0w, l0b, xs0);
    size_t base = (size_t)n * FD + lane * 8;
    st8(g_d + base, xs0);
    float xs[8];
    ln_regs(xs0, lane, lw, lb, xs);
    mix3_store(xs, lane, base, tmk, tmv, tmr, sp);
}

__global__ void ln_mix2_kernel(const float* __restrict__ lw, const float* __restrict__ lb,
                               const float* __restrict__ tmk, const float* __restrict__ tmr,
                               const float* __restrict__ sp) {
    int n = blockIdx.x * 8 + (threadIdx.x >> 5);
    int lane = threadIdx.x & 31;
    float xs[8];
    ln_compute(n, lane, lw, lb, xs);
    size_t base = (size_t)n * FD + lane * 8;
    int j = lane * 8;
    float spv[8], mk[8], mr[8];
    ld8(sp + base, spv); ld8(tmk + j, mk); ld8(tmr + j, mr);
    float ok[8], orr[8];
#pragma unroll
    for (int t = 0; t < 8; t++) {
        ok[t]  = xs[t] * mk[t] + spv[t] * (1.f - mk[t]);
        orr[t] = xs[t] * mr[t] + spv[t] * (1.f - mr[t]);
    }
    st8h(g_xkh + base, ok); st8h(g_xrh + base, orr);
}

// ---------------- WKV single step + sigmoid gate (4 elems/thread) ----------------
__global__ void wkv_kernel(const float* __restrict__ tf, const float* __restrict__ aa,
                           const float* __restrict__ bb, const float* __restrict__ pp) {
    size_t idx = ((size_t)blockIdx.x * 256 + threadIdx.x) * 4;
    int c = (int)(idx & (FD - 1));
    float4 k4 = *(const float4*)&g_k[idx];
    float4 v4 = *(const float4*)&g_v[idx];
    float4 r4 = *(const float4*)&g_r[idx];
    float4 tf4 = *(const float4*)&tf[c];
    float4 aa4 = *(const float4*)&aa[idx];
    float4 bb4 = *(const float4*)&bb[idx];
    float4 pp4 = *(const float4*)&pp[idx];
    float o[4];
    float kk[4] = {k4.x, k4.y, k4.z, k4.w};
    float vv[4] = {v4.x, v4.y, v4.z, v4.w};
    float rr[4] = {r4.x, r4.y, r4.z, r4.w};
    float tfv[4] = {tf4.x, tf4.y, tf4.z, tf4.w};
    float aav[4] = {aa4.x, aa4.y, aa4.z, aa4.w};
    float bbv[4] = {bb4.x, bb4.y, bb4.z, bb4.w};
    float ppv[4] = {pp4.x, pp4.y, pp4.z, pp4.w};
#pragma unroll
    for (int t = 0; t < 4; t++) {
        float ww = tfv[t] + kk[t];
        float p = fmaxf(ppv[t], ww);
        float e1 = expf(ppv[t] - p), e2 = expf(ww - p);
        float wkv = (e1 * aav[t] + e2 * vv[t]) / (e1 * bbv[t] + e2);
        float sig = 1.f / (1.f + expf(-rr[t]));
        o[t] = sig * wkv;
    }
    union { __half2 h[2]; uint2 u; } out;
    out.h[0] = __floats2half2_rn(o[0], o[1]);
    out.h[1] = __floats2half2_rn(o[2], o[3]);
    *(uint2*)&g_gateh[idx] = out.u;
}

// ---------------- depthwise 7x7 ----------------
__global__ void wt_all_kernel(const float* __restrict__ wt) {
    int l = blockIdx.y, tap = blockIdx.x, c = threadIdx.x;
    g_wtT[(l * 49 + tap) * FD + c] = wt[(l * FD + c) * 49 + tap];
}

__global__ __launch_bounds__(256)
void dw7t_kernel(const float* __restrict__ bias, const float* __restrict__ wtT) {
    __shared__ float tile[22 * 22 * 16];
    __shared__ float ws[49 * 16];
    __shared__ float bs[16];
    const int w0 = blockIdx.x * 16, h0 = blockIdx.y * 16, cb = blockIdx.z * 16;
    const int tid = threadIdx.x;

    if (tid < 196) {
        int t = tid >> 2, c4 = (tid & 3) * 4;
        *(float4*)&ws[t * 16 + c4] = *(const float4*)&wtT[t * FD + cb + c4];
    }
    if (tid < 16) bs[tid] = bias[cb + tid];

    for (int idx = tid; idx < 22 * 22 * 4; idx += 256) {
        int pos = idx >> 2, c4 = (idx & 3) * 4;
        int ih = pos / 22, iw = pos % 22;
        int gh = h0 + ih - 3, gw = w0 + iw - 3;
        float4 v{0.f, 0.f, 0.f, 0.f};
        if (gh >= 0 && gh < IMH && gw >= 0 && gw < IMW)
            v = *(const float4*)&g_d[((size_t)gh * IMW + gw) * FD + cb + c4];
        *(float4*)&tile[pos * 16 + c4] = v;
    }
    __syncthreads();

    const int c4id = tid & 3;
    const int sbase = tid >> 2;
    float acc[4][4];
    float4 bv = *(const float4*)&bs[c4id * 4];
#pragma unroll
    for (int j = 0; j < 4; j++) { acc[j][0] = bv.x; acc[j][1] = bv.y; acc[j][2] = bv.z; acc[j][3] = bv.w; }

#pragma unroll
    for (int u = 0; u < 7; u++) {
#pragma unroll
        for (int v7 = 0; v7 < 7; v7++) {
            float4 wv = *(const float4*)&ws[(u * 7 + v7) * 16 + c4id * 4];
#pragma unroll
            for (int j = 0; j < 4; j++) {
                int s = sbase + 64 * j;
                int sy = s >> 4, sx = s & 15;
                float4 tv = *(const float4*)&tile[((sy + u) * 22 + (sx + v7)) * 16 + c4id * 4];
                acc[j][0] += tv.x * wv.x; acc[j][1] += tv.y * wv.y;
                acc[j][2] += tv.z * wv.z; acc[j][3] += tv.w * wv.w;
            }
        }
    }
#pragma unroll
    for (int j = 0; j < 4; j++) {
        int s = sbase + 64 * j;
        int sy = s >> 4, sx = s & 15;
        union { __half2 h[2]; uint2 u; } t;
        t.h[0] = __floats2half2_rn(acc[j][0], acc[j][1]);
        t.h[1] = __floats2half2_rn(acc[j][2], acc[j][3]);
        *(uint2*)&g_dwh[((size_t)(h0 + sy) * IMW + (w0 + sx)) * FD + cb + c4id * 4] = t.u;
    }
}

// ---------------- FP16 tensor-core NT GEMM, ldmatrix + 3-stage cp.async ----------------
#define BM 128
#define BN 128
#define BKH 32                         // k per tile (halfs)
#define SROWH 40                       // padded row stride (halfs) = 80 bytes
#define SSTRIDEH ((BM + BN) * SROWH)   // halfs per stage (10240)
#define GSMEM (3 * SSTRIDEH * 2)       // bytes (61440)

__device__ __forceinline__ void mma_f16(float c[4], const uint32_t a[4], const uint32_t b[2]) {
    asm volatile(
        "mma.sync.aligned.m16n8k16.row.col.f32.f16.f16.f32 "
        "{%0,%1,%2,%3}, {%4,%5,%6,%7}, {%8,%9}, {%0,%1,%2,%3};"
        : "+f"(c[0]), "+f"(c[1]), "+f"(c[2]), "+f"(c[3])
        : "r"(a[0]), "r"(a[1]), "r"(a[2]), "r"(a[3]), "r"(b[0]), "r"(b[1]));
}

__device__ __forceinline__ void ldsm4(uint32_t r[4], uint32_t addr) {
    asm volatile("ldmatrix.sync.aligned.m8n8.x4.shared.b16 {%0,%1,%2,%3}, [%4];"
                 : "=r"(r[0]), "=r"(r[1]), "=r"(r[2]), "=r"(r[3]) : "r"(addr));
}

__device__ __forceinline__ void cp16(__half* smem, const __half* g) {
    uint32_t s = (uint32_t)__cvta_generic_to_shared(smem);
    asm volatile("cp.async.cg.shared.global [%0], [%1], 16;" :: "r"(s), "l"(g));
}

// EPI 0: C(float)=acc | 1: Ch=sigmoid | 2: Ch=relu^2 | 3: D+=acc | 4: D+=aux(half)*acc | 5: D+=acc+bias
template <int EPI>
__device__ __forceinline__ void gemm_body(
    const __half* __restrict__ A, const __half* __restrict__ Wm,
    float* __restrict__ C, __half* __restrict__ Ch, float* __restrict__ D,
    const __half* __restrict__ aux, const float* __restrict__ bias,
    int M, int Nout, int K, __half* smemh) {

    const int tid  = threadIdx.x;
    const int bm   = blockIdx.y * BM;
    const int bn   = blockIdx.x * BN;
    const int wid  = tid >> 5;
    const int lane = tid & 31;
    const int wm   = wid & 1;
    const int wn   = wid >> 1;
    const int g    = lane >> 2;
    const int tg   = lane & 3;

    const int lrow = tid >> 1;            // 0..127
    const int lkc  = (tid & 1) * 16;      // 0 or 16 halfs

    const __half* Ab = A  + (size_t)(bm + lrow) * K + lkc;
    const __half* Bb = Wm + (size_t)(bn + lrow) * K + lkc;
    __half* const sA = smemh + lrow * SROWH + lkc;
    __half* const sB = smemh + BM * SROWH + lrow * SROWH + lkc;

    const uint32_t smem_u = (uint32_t)__cvta_generic_to_shared(smemh);
    // ldmatrix lane addressing (bytes)
    const uint32_t a_lrow = (uint32_t)(lane & 15);
    const uint32_t a_koff = ((lane >> 4) & 1) * 16;
    const uint32_t b_lrow = (uint32_t)((lane & 7) + ((lane & 16) ? 8 : 0));
    const uint32_t b_koff = (lane & 8) ? 16 : 0;

    float acc[4][4][4];
#pragma unroll
    for (int i = 0; i < 4; i++)
#pragma unroll
        for (int j = 0; j < 4; j++)
#pragma unroll
            for (int t = 0; t < 4; t++) acc[i][j][t] = 0.f;

    const int nk = K / BKH;

    cp16(sA, Ab); cp16(sA + 8, Ab + 8);
    cp16(sB, Bb); cp16(sB + 8, Bb + 8);
    asm volatile("cp.async.commit_group;");
    cp16(sA + SSTRIDEH, Ab + BKH); cp16(sA + SSTRIDEH + 8, Ab + BKH + 8);
    cp16(sB + SSTRIDEH, Bb + BKH); cp16(sB + SSTRIDEH + 8, Bb + BKH + 8);
    asm volatile("cp.async.commit_group;");

    int cur = 0;
    for (int kt = 0; kt < nk; kt++) {
        asm volatile("cp.async.wait_group 1;");
        __syncthreads();
        int pf = kt + 2;
        if (pf < nk) {
            int ps = cur + 2; if (ps >= 3) ps -= 3;
            const __half* ga = Ab + pf * BKH;
            const __half* gb = Bb + pf * BKH;
            __half* pa = sA + ps * SSTRIDEH;
            __half* pb = sB + ps * SSTRIDEH;
            cp16(pa, ga); cp16(pa + 8, ga + 8);
            cp16(pb, gb); cp16(pb + 8, gb + 8);
        }
        asm volatile("cp.async.commit_group;");

        const uint32_t stage = smem_u + (uint32_t)cur * (SSTRIDEH * 2);
        const uint32_t aBase = stage;
        const uint32_t bBase = stage + BM * (SROWH * 2);
#pragma unroll
        for (int kk = 0; kk < 2; kk++) {
            uint32_t af[4][4], bf[4][2];
#pragma unroll
            for (int mt = 0; mt < 4; mt++) {
                uint32_t addr = aBase + (uint32_t)(wm * 64 + mt * 16 + a_lrow) * 80
                              + (uint32_t)kk * 32 + a_koff;
                ldsm4(af[mt], addr);
            }
#pragma unroll
            for (int pr = 0; pr < 2; pr++) {
                uint32_t addr = bBase + (uint32_t)(wn * 32 + pr * 16 + b_lrow) * 80
                              + (uint32_t)kk * 32 + b_koff;
                uint32_t t4[4];
                ldsm4(t4, addr);
                bf[pr * 2][0] = t4[0]; bf[pr * 2][1] = t4[1];
                bf[pr * 2 + 1][0] = t4[2]; bf[pr * 2 + 1][1] = t4[3];
            }
#pragma unroll
            for (int mt = 0; mt < 4; mt++)
#pragma unroll
                for (int nt = 0; nt < 4; nt++)
                    mma_f16(acc[mt][nt], af[mt], bf[nt]);
        }
        cur++; if (cur == 3) cur = 0;
    }

    // epilogue
#pragma unroll
    for (int mt = 0; mt < 4; mt++) {
#pragma unroll
        for (int nt = 0; nt < 4; nt++) {
            int row0 = bm + wm * 64 + mt * 16 + g;
            int col0 = bn + wn * 32 + nt * 8 + 2 * tg;
#pragma unroll
            for (int h = 0; h < 2; h++) {
                int row = row0 + h * 8;
                float rx = acc[mt][nt][2 * h], ry = acc[mt][nt][2 * h + 1];
                size_t off = (size_t)row * Nout + col0;
                if (EPI == 0) {
                    *(float2*)&C[off] = float2{rx, ry};
                } else if (EPI == 1) {
                    rx = 1.f / (1.f + expf(-rx));
                    ry = 1.f / (1.f + expf(-ry));
                    *(__half2*)&Ch[off] = __floats2half2_rn(rx, ry);
                } else if (EPI == 2) {
                    rx = fmaxf(rx, 0.f); rx *= rx;
                    ry = fmaxf(ry, 0.f); ry *= ry;
                    *(__half2*)&Ch[off] = __floats2half2_rn(rx, ry);
                } else if (EPI == 3) {
                    float2 dc = *(float2*)&D[off];
                    dc.x += rx; dc.y += ry;
                    *(float2*)&D[off] = dc;
                } else if (EPI == 4) {
                    __half2 av = *(const __half2*)&aux[off];
                    float2 afv = __half22float2(av);
                    float2 dc = *(float2*)&D[off];
                    dc.x += afv.x * rx; dc.y += afv.y * ry;
                    *(float2*)&D[off] = dc;
                } else if (EPI == 5) {
                    float2 bv = *(const float2*)&bias[col0];
                    float2 dc = *(float2*)&D[off];
                    dc.x += rx + bv.x; dc.y += ry + bv.y;
                    *(float2*)&D[off] = dc;
                }
            }
        }
    }
}

template <int EPI>
__global__ __launch_bounds__(256, 2)
void gemm_h(const __half* A, const __half* W, float* C, __half* Ch, float* D,
            const __half* aux, const float* bias, int M, int Nout, int K) {
    extern __shared__ __half sh[];
    gemm_body<EPI>(A, W, C, Ch, D, aux, bias, M, Nout, K, sh);
}

struct Ptr3 {
    const __half* A[3];
    const __half* W[3];
    float* C[3];
};

__global__ __launch_bounds__(256, 2)
void gemm_kvr(Ptr3 p, int M, int Nout, int K) {
    extern __shared__ __half sh[];
    int z = blockIdx.z;
    gemm_body<0>(p.A[z], p.W[z], p.C[z], nullptr, nullptr, nullptr, nullptr, M, Nout, K, sh);
}

// ---------------- output transpose [N,F] -> [F,N] ----------------
__global__ void out_transpose(float* __restrict__ out) {
    __shared__ float tile[32][33];
    int bn = blockIdx.x * 32;
    int bc = blockIdx.y * 32;
    int tx = threadIdx.x, ty = threadIdx.y;
#pragma unroll
    for (int j = 0; j < 32; j += 8)
        tile[ty + j][tx] = g_d[(size_t)(bn + ty + j) * FD + bc + tx];
    __syncthreads();
#pragma unroll
    for (int j = 0; j < 32; j += 8)
        out[(size_t)(bc + ty + j) * NTOK + bn + tx] = tile[tx][ty + j];
}

// ---------------- host orchestration ----------------
extern "C" void kernel_launch(void* const* d_in, const int* in_sizes, int n_in,
                              void* d_out, int out_size) {
    auto IN = [&](int i) { return (const float*)d_in[i]; };
    const float* x    = IN(0);
    const float* cw1  = IN(1);
    const float* cb1  = IN(2);
    const float* cw2  = IN(3);
    const float* cb2  = IN(4);
    const float* ln0w = IN(5);
    const float* ln0b = IN(6);
    const float* ln1w = IN(7);
    const float* ln1b = IN(8);
    const float* ln2w = IN(9);
    const float* ln2b = IN(10);
    const float* atmk = IN(11);
    const float* atmv = IN(12);
    const float* atmr = IN(13);
    bool sig = (in_sizes[16] > 2048);
    const float *atf, *akw, *avw, *arw, *aow, *ftmk, *ftmr, *fkw, *fvw, *frw;
    if (sig) {
        atf = IN(14);
        akw = IN(16); avw = IN(17); arw = IN(18); aow = IN(19);
        ftmk = IN(20); ftmr = IN(21);
        fkw = IN(22); fvw = IN(23); frw = IN(24);
    } else {
        ftmk = IN(14); ftmr = IN(15);
        atf = IN(16);
        akw = IN(18); avw = IN(19); arw = IN(20); aow = IN(21);
        frw = IN(22); fkw = IN(23); fvw = IN(24);
    }
    const float* sdww = IN(25);
    const float* sdwb = IN(26);
    const float* spww = IN(27);
    const float* spwb = IN(28);
    const float* st   = IN(29);

    float *pd, *pk, *pv, *pr, *pwt;
    __half *pxk, *pxv, *pxr, *pgate, *prr, *phid, *pdw, *pw;
    cudaGetSymbolAddress((void**)&pd,    g_d);
    cudaGetSymbolAddress((void**)&pxk,   g_xkh);
    cudaGetSymbolAddress((void**)&pxv,   g_xvh);
    cudaGetSymbolAddress((void**)&pxr,   g_xrh);
    cudaGetSymbolAddress((void**)&pk,    g_k);
    cudaGetSymbolAddress((void**)&pv,    g_v);
    cudaGetSymbolAddress((void**)&pr,    g_r);
    cudaGetSymbolAddress((void**)&pgate, g_gateh);
    cudaGetSymbolAddress((void**)&prr,   g_rrh);
    cudaGetSymbolAddress((void**)&phid,  g_hidh);
    cudaGetSymbolAddress((void**)&pdw,   g_dwh);
    cudaGetSymbolAddress((void**)&pw,    g_wbh);
    cudaGetSymbolAddress((void**)&pwt,   g_wtT);

    cudaFuncSetAttribute(gemm_h<1>, cudaFuncAttributeMaxDynamicSharedMemorySize, GSMEM);
    cudaFuncSetAttribute(gemm_h<2>, cudaFuncAttributeMaxDynamicSharedMemorySize, GSMEM);
    cudaFuncSetAttribute(gemm_h<3>, cudaFuncAttributeMaxDynamicSharedMemorySize, GSMEM);
    cudaFuncSetAttribute(gemm_h<4>, cudaFuncAttributeMaxDynamicSharedMemorySize, GSMEM);
    cudaFuncSetAttribute(gemm_h<5>, cudaFuncAttributeMaxDynamicSharedMemorySize, GSMEM);
    cudaFuncSetAttribute(gemm_kvr,  cudaFuncAttributeMaxDynamicSharedMemorySize, GSMEM);

    const dim3 g256(FD / BN, NTOK / BM);       // (2, 200)
    const dim3 gkvr(FD / BN, NTOK / BM, 3);    // (2, 200, 3)
    const dim3 g1024(FHID / BN, NTOK / BM);    // (8, 200)
    const dim3 gdw(IMW / 16, IMH / 16, FD / 16);
    const size_t NF = (size_t)NTOK * FD;

    // 1: all weight conversions in one launch
    Src8 s8;
    s8.p[0] = akw; s8.p[1] = avw; s8.p[2] = arw; s8.p[3] = aow;
    s8.p[4] = frw; s8.p[5] = spww; s8.p[6] = fkw; s8.p[7] = fvw;
    cvt_all_kernel<<<1792, 256>>>(s8);
    // 2: stem
    stem_kernel<<<NTOK, 256>>>(x, cw1, cb1, cw2, cb2);
    // 3: ln0 + ln1 + mix (layer 0)
    ln_first_mix3_kernel<<<NTOK / 8, 256>>>(ln0w, ln0b, ln1w, ln1b,
                                            atmk, atmv, atmr, st + 1 * NF);
    // 4: first GEMM (profiled by ncu window)
    {
        Ptr3 p3;
        p3.A[0] = pxk; p3.A[1] = pxv; p3.A[2] = pxr;
        p3.W[0] = pw + O_AKW; p3.W[1] = pw + O_AVW; p3.W[2] = pw + O_ARW;
        p3.C[0] = pk; p3.C[1] = pv; p3.C[2] = pr;
        gemm_kvr<<<gkvr, 256, GSMEM>>>(p3, NTOK, FD, FD);
    }
    wt_all_kernel<<<dim3(49, NL), 256>>>(sdww);

    for (int i = 0; i < NL; i++) {
        const float* sp0 = st + (size_t)(5 * i + 0) * NF;
        const float* sp1 = st + (size_t)(5 * i + 1) * NF;
        const float* aa  = st + (size_t)(5 * i + 2) * NF;
        const float* bb  = st + (size_t)(5 * i + 3) * NF;
        const float* pp  = st + (size_t)(5 * i + 4) * NF;
        const size_t wo256 = (size_t)i * FD * FD;
        const size_t wo1k  = (size_t)i * FHID * FD;

        // --- attention (single-step WKV) ---
        if (i > 0) {
            ln_mix3_kernel<<<NTOK / 8, 256>>>(ln1w + i * FD, ln1b + i * FD,
                                              atmk + i * FD, atmv + i * FD, atmr + i * FD, sp1);
            Ptr3 p3;
            p3.A[0] = pxk; p3.A[1] = pxv; p3.A[2] = pxr;
            p3.W[0] = pw + O_AKW + wo256; p3.W[1] = pw + O_AVW + wo256; p3.W[2] = pw + O_ARW + wo256;
            p3.C[0] = pk; p3.C[1] = pv; p3.C[2] = pr;
            gemm_kvr<<<gkvr, 256, GSMEM>>>(p3, NTOK, FD, FD);
        }
        wkv_kernel<<<NTOK * FD / 1024, 256>>>(atf + i * FD, aa, bb, pp);
        gemm_h<3><<<g256, 256, GSMEM>>>(pgate, pw + O_AOW + wo256, nullptr, nullptr, pd, nullptr, nullptr, NTOK, FD, FD);

        // --- FFN (squared-relu channel mix) ---
        ln_mix2_kernel<<<NTOK / 8, 256>>>(ln2w + i * FD, ln2b + i * FD,
                                          ftmk + i * FD, ftmr + i * FD, sp0);
        gemm_h<2><<<g1024, 256, GSMEM>>>(pxk, pw + O_FKW + wo1k, nullptr, phid, nullptr, nullptr, nullptr, NTOK, FHID, FD);
        gemm_h<1><<<g256, 256, GSMEM>>>(pxr, pw + O_FRW + wo256, nullptr, prr, nullptr, nullptr, nullptr, NTOK, FD, FD);
        gemm_h<4><<<g256, 256, GSMEM>>>(phid, pw + O_FVW + wo1k, nullptr, nullptr, pd, prr, nullptr, NTOK, FD, FHID);

        // --- spatial residual ---
        dw7t_kernel<<<gdw, 256>>>(sdwb + i * FD, pwt + (size_t)i * 49 * FD);
        gemm_h<5><<<g256, 256, GSMEM>>>(pdw, pw + O_SPW + wo256, nullptr, nullptr, pd, nullptr, spwb + i * FD, NTOK, FD, FD);
    }

    out_transpose<<<dim3(NTOK / 32, FD / 32), dim3(32, 8)>>>((float*)d_out);
}